// round 2
// baseline (speedup 1.0000x reference)
#include <cuda_runtime.h>
#include <math_constants.h>

// Problem constants
#define B_SZ   8
#define T_SZ   2048
#define C_SZ   1024
#define H_SZ   128
#define ROWS   (B_SZ * T_SZ)       // 16384
#define SCALE  (0.03125f)          // C^-0.5 = 1/32

// Scratch for q, k, v projections (device static arrays: allocation-free rule)
__device__ float g_q[ROWS * H_SZ];
__device__ float g_k[ROWS * H_SZ];
__device__ float g_v[ROWS * H_SZ];

// ---------------------------------------------------------------------------
// Projection GEMM: out[M=16384, N=128] = x[M,1024] @ W[1024,128]
// Tile: BM=64, BN=128, BK=32; 128 threads, each computes 8x8 register tile.
// blockIdx.y in {0,1,2} selects Wq/Wk/Wv -> g_q/g_k/g_v.
// ---------------------------------------------------------------------------
#define PBM 64
#define PBK 32

__global__ __launch_bounds__(128) void proj_kernel(
    const float* __restrict__ x,
    const float* __restrict__ Wq,
    const float* __restrict__ Wk,
    const float* __restrict__ Wv)
{
    const float* __restrict__ W =
        (blockIdx.y == 0) ? Wq : (blockIdx.y == 1) ? Wk : Wv;
    float* __restrict__ out =
        (blockIdx.y == 0) ? g_q : (blockIdx.y == 1) ? g_k : g_v;

    __shared__ float As[PBM][PBK + 1];   // 64 x 33 (pad avoids conflicts)
    __shared__ float Bs[PBK][H_SZ];      // 32 x 128

    const int tid = threadIdx.x;
    const int ty  = tid >> 4;            // 0..7  (row group: rows ty*8..+7)
    const int tx  = tid & 15;            // 0..15 (col group: cols tx*8..+7)
    const int row0 = blockIdx.x * PBM;

    float acc[8][8];
#pragma unroll
    for (int i = 0; i < 8; i++)
#pragma unroll
        for (int j = 0; j < 8; j++) acc[i][j] = 0.0f;

    for (int k0 = 0; k0 < C_SZ; k0 += PBK) {
        // Load A tile: 64x32 floats = 512 float4, 128 threads -> 4 each
#pragma unroll
        for (int i = 0; i < 4; i++) {
            int idx = i * 128 + tid;          // float4 index 0..511
            int m   = idx >> 3;               // 8 float4 per row
            int kk  = (idx & 7) << 2;
            float4 v = *(const float4*)&x[(size_t)(row0 + m) * C_SZ + k0 + kk];
            As[m][kk + 0] = v.x; As[m][kk + 1] = v.y;
            As[m][kk + 2] = v.z; As[m][kk + 3] = v.w;
        }
        // Load B tile: 32x128 floats = 1024 float4, 128 threads -> 8 each
#pragma unroll
        for (int i = 0; i < 8; i++) {
            int idx = i * 128 + tid;          // float4 index 0..1023
            int kk  = idx >> 5;               // 32 float4 per row
            int n   = (idx & 31) << 2;
            *(float4*)&Bs[kk][n] = *(const float4*)&W[(size_t)(k0 + kk) * H_SZ + n];
        }
        __syncthreads();

#pragma unroll
        for (int kk = 0; kk < PBK; kk++) {
            float b[8];
            float4 b0 = *(float4*)&Bs[kk][tx * 8];
            float4 b1 = *(float4*)&Bs[kk][tx * 8 + 4];
            b[0]=b0.x; b[1]=b0.y; b[2]=b0.z; b[3]=b0.w;
            b[4]=b1.x; b[5]=b1.y; b[6]=b1.z; b[7]=b1.w;
            float a[8];
#pragma unroll
            for (int i = 0; i < 8; i++) a[i] = As[ty * 8 + i][kk];
#pragma unroll
            for (int i = 0; i < 8; i++)
#pragma unroll
                for (int j = 0; j < 8; j++)
                    acc[i][j] += a[i] * b[j];
        }
        __syncthreads();
    }

    // Write 8x8 tile
#pragma unroll
    for (int i = 0; i < 8; i++) {
        size_t base = (size_t)(row0 + ty * 8 + i) * H_SZ + tx * 8;
        float4 o0 = make_float4(acc[i][0], acc[i][1], acc[i][2], acc[i][3]);
        float4 o1 = make_float4(acc[i][4], acc[i][5], acc[i][6], acc[i][7]);
        *(float4*)&out[base]     = o0;
        *(float4*)&out[base + 4] = o1;
    }
}

// ---------------------------------------------------------------------------
// Flash attention (fp32, online softmax).
// Block = 128 threads handles BQ=16 query rows of one batch.
// K/V processed in chunks of CK=32 keys.
//   score phase: thread (qg=tid/32, j=tid%32) computes 4 (qi,j) dots
//   softmax:     threads 0..15 each own one query row
//   output:      thread d=tid accumulates out column d for all 16 rows
// Heavy tiles (large t0) scheduled first to minimize wave-tail imbalance.
// ---------------------------------------------------------------------------
#define BQ 16
#define CK 32

__global__ __launch_bounds__(128) void attn_kernel(float* __restrict__ out)
{
    __shared__ float sq[BQ][H_SZ];       // 8 KB
    __shared__ float sk[CK][H_SZ + 1];   // 16.5 KB, pad for conflict-free
    __shared__ float sv[CK][H_SZ + 1];   // 16.5 KB
    __shared__ float sp[BQ][36];         // probs, pad 36 (16B-aligned rows)
    __shared__ float s_corr[BQ];
    __shared__ float s_l[BQ];

    const int tid = threadIdx.x;
    const int blk = blockIdx.x;          // 1024 blocks
    const int b   = blk >> 7;            // batch
    const int ti  = blk & 127;
    const int t0  = (127 - ti) * BQ;     // heavy (large t) first

    const float* __restrict__ qb = g_q + ((size_t)b * T_SZ + t0) * H_SZ;
    const float* __restrict__ kb = g_k + (size_t)b * T_SZ * H_SZ;
    const float* __restrict__ vb = g_v + (size_t)b * T_SZ * H_SZ;

    // Load Q tile: 16x128 floats = 512 float4, 128 threads -> 4 each
#pragma unroll
    for (int i = 0; i < 4; i++) {
        int idx = i * 128 + tid;         // float4 index
        int qi  = idx >> 5;
        int d   = (idx & 31) << 2;
        *(float4*)&sq[qi][d] = *(const float4*)&qb[(size_t)qi * H_SZ + d];
    }

    float m_run = -CUDART_INF_F;   // meaningful only for tid < 16
    float l_run = 0.0f;
    float acc[BQ];
#pragma unroll
    for (int q = 0; q < BQ; q++) acc[q] = 0.0f;

    const int t_max = t0 + BQ - 1;
    const int qg = tid >> 5;             // 0..3
    const int j  = tid & 31;             // key within chunk
    const int qbase = qg * 4;

    for (int s = 0; s <= t_max; s += CK) {
        __syncthreads();   // protect smem from previous-iter readers

        // Load K,V chunk: 32x128 floats each = 1024 float4 each,
        // 128 threads -> 8 float4 each per tile.
#pragma unroll
        for (int i = 0; i < 8; i++) {
            int idx = i * 128 + tid;     // float4 index 0..1023
            int r   = idx >> 5;          // 32 float4 (=128 floats) per row
            int d   = (idx & 31) << 2;
            float4 kv = *(const float4*)&kb[(size_t)(s + r) * H_SZ + d];
            sk[r][d+0] = kv.x; sk[r][d+1] = kv.y; sk[r][d+2] = kv.z; sk[r][d+3] = kv.w;
            float4 vv = *(const float4*)&vb[(size_t)(s + r) * H_SZ + d];
            sv[r][d+0] = vv.x; sv[r][d+1] = vv.y; sv[r][d+2] = vv.z; sv[r][d+3] = vv.w;
        }
        __syncthreads();

        // ---- score phase: 4 (qi, j) pairs per thread ----
        float sc0 = 0.f, sc1 = 0.f, sc2 = 0.f, sc3 = 0.f;
#pragma unroll 8
        for (int d = 0; d < H_SZ; d++) {
            float kv = sk[j][d];
            sc0 += sq[qbase + 0][d] * kv;
            sc1 += sq[qbase + 1][d] * kv;
            sc2 += sq[qbase + 2][d] * kv;
            sc3 += sq[qbase + 3][d] * kv;
        }
        {
            float scv[4] = {sc0, sc1, sc2, sc3};
#pragma unroll
            for (int q = 0; q < 4; q++) {
                int qi = qbase + q;
                float val = scv[q] * SCALE;
                if (s + j > t0 + qi) val = -CUDART_INF_F;   // causal mask
                sp[qi][j] = val;
            }
        }
        __syncthreads();

        // ---- online softmax: threads 0..15, one per query row ----
        if (tid < BQ) {
            float mc = -CUDART_INF_F;
#pragma unroll
            for (int jj = 0; jj < CK; jj++) mc = fmaxf(mc, sp[tid][jj]);
            float mn = fmaxf(m_run, mc);
            float corr = __expf(m_run - mn);   // first chunk: exp(-inf)=0
            float ls = 0.0f;
#pragma unroll
            for (int jj = 0; jj < CK; jj++) {
                float p = __expf(sp[tid][jj] - mn);
                sp[tid][jj] = p;
                ls += p;
            }
            l_run = l_run * corr + ls;
            m_run = mn;
            s_corr[tid] = corr;
        }
        __syncthreads();

        // ---- output accumulation: thread owns column d = tid ----
#pragma unroll
        for (int q = 0; q < BQ; q++) acc[q] *= s_corr[q];
#pragma unroll
        for (int jj = 0; jj < CK; jj += 4) {
            float v0 = sv[jj + 0][tid];
            float v1 = sv[jj + 1][tid];
            float v2 = sv[jj + 2][tid];
            float v3 = sv[jj + 3][tid];
#pragma unroll
            for (int q = 0; q < BQ; q++) {
                float4 p = *(float4*)&sp[q][jj];
                acc[q] += p.x * v0 + p.y * v1 + p.z * v2 + p.w * v3;
            }
        }
    }

    __syncthreads();
    if (tid < BQ) s_l[tid] = l_run;
    __syncthreads();

#pragma unroll
    for (int q = 0; q < BQ; q++) {
        out[((size_t)b * T_SZ + t0 + q) * H_SZ + tid] = acc[q] / s_l[q];
    }
}

// ---------------------------------------------------------------------------
extern "C" void kernel_launch(void* const* d_in, const int* in_sizes, int n_in,
                              void* d_out, int out_size)
{
    const float* x  = (const float*)d_in[0];   // [8,2048,1024]
    const float* Wq = (const float*)d_in[1];   // [1024,128]
    const float* Wk = (const float*)d_in[2];
    const float* Wv = (const float*)d_in[3];
    float* out = (float*)d_out;                // [8,2048,128]

    proj_kernel<<<dim3(ROWS / PBM, 3), 128>>>(x, Wq, Wk, Wv);
    attn_kernel<<<(ROWS / BQ), 128>>>(out);
}

// round 4
// speedup vs baseline: 4.0244x; 4.0244x over previous
#include <cuda_runtime.h>
#include <cuda_bf16.h>
#include <cstdint>

// Problem constants
#define B_SZ   8
#define T_SZ   2048
#define C_SZ   1024
#define H_SZ   128
#define ROWS   (B_SZ * T_SZ)       // 16384
#define SCALE  (0.03125f)          // C^-0.5 = 1/32

// Scratch (device statics: allocation-free rule)
__device__ __nv_bfloat16 g_xh[ROWS * C_SZ];
__device__ __nv_bfloat16 g_xl[ROWS * C_SZ];
__device__ __nv_bfloat16 g_wth[3 * H_SZ * C_SZ];   // W^T split: [proj][n][k]
__device__ __nv_bfloat16 g_wtl[3 * H_SZ * C_SZ];
__device__ __nv_bfloat16 g_qh[ROWS * H_SZ];        // q scaled by 1/32, split
__device__ __nv_bfloat16 g_ql[ROWS * H_SZ];
__device__ __nv_bfloat16 g_kh[ROWS * H_SZ];
__device__ __nv_bfloat16 g_kl[ROWS * H_SZ];
__device__ __nv_bfloat16 g_vh[ROWS * H_SZ];
__device__ __nv_bfloat16 g_vl[ROWS * H_SZ];

// ---------------------------------------------------------------------------
// Helpers: mma.sync (sm_80+ PTX; valid under compute_103) + ldmatrix
// ---------------------------------------------------------------------------
__device__ __forceinline__ uint32_t smem_u32(const void* p) {
    uint32_t a;
    asm("{ .reg .u64 t; cvta.to.shared.u64 t, %1; cvt.u32.u64 %0, t; }"
        : "=r"(a) : "l"(p));
    return a;
}
__device__ __forceinline__ void ldsm4(uint32_t* r, uint32_t addr) {
    asm volatile("ldmatrix.sync.aligned.m8n8.x4.shared.b16 {%0,%1,%2,%3}, [%4];"
                 : "=r"(r[0]), "=r"(r[1]), "=r"(r[2]), "=r"(r[3]) : "r"(addr));
}
__device__ __forceinline__ void ldsm4t(uint32_t* r, uint32_t addr) {
    asm volatile("ldmatrix.sync.aligned.m8n8.x4.trans.shared.b16 {%0,%1,%2,%3}, [%4];"
                 : "=r"(r[0]), "=r"(r[1]), "=r"(r[2]), "=r"(r[3]) : "r"(addr));
}
__device__ __forceinline__ void mma16816(float* d, const uint32_t* a,
                                         uint32_t b0, uint32_t b1) {
    asm volatile(
        "mma.sync.aligned.m16n8k16.row.col.f32.bf16.bf16.f32 "
        "{%0,%1,%2,%3}, {%4,%5,%6,%7}, {%8,%9}, {%0,%1,%2,%3};"
        : "+f"(d[0]), "+f"(d[1]), "+f"(d[2]), "+f"(d[3])
        : "r"(a[0]), "r"(a[1]), "r"(a[2]), "r"(a[3]), "r"(b0), "r"(b1));
}
// pack two fp32 -> bf16x2 (lo in low half)
__device__ __forceinline__ uint32_t pack_bf16(float lo, float hi) {
    uint32_t r;
    asm("cvt.rn.bf16x2.f32 %0, %1, %2;" : "=r"(r) : "f"(hi), "f"(lo));
    return r;
}

// ---------------------------------------------------------------------------
// prep_x: split x (fp32) into bf16 hi/lo pair
// ---------------------------------------------------------------------------
__global__ __launch_bounds__(256) void prep_x(const float* __restrict__ x)
{
    size_t i = (size_t)blockIdx.x * 256 + threadIdx.x;   // float4 index
    float4 v = ((const float4*)x)[i];
    __nv_bfloat16 h0 = __float2bfloat16(v.x);
    __nv_bfloat16 h1 = __float2bfloat16(v.y);
    __nv_bfloat16 h2 = __float2bfloat16(v.z);
    __nv_bfloat16 h3 = __float2bfloat16(v.w);
    __nv_bfloat16 l0 = __float2bfloat16(v.x - __bfloat162float(h0));
    __nv_bfloat16 l1 = __float2bfloat16(v.y - __bfloat162float(h1));
    __nv_bfloat16 l2 = __float2bfloat16(v.z - __bfloat162float(h2));
    __nv_bfloat16 l3 = __float2bfloat16(v.w - __bfloat162float(h3));
    __nv_bfloat162* dh = (__nv_bfloat162*)g_xh;
    __nv_bfloat162* dl = (__nv_bfloat162*)g_xl;
    dh[2 * i]     = __nv_bfloat162(h0, h1);
    dh[2 * i + 1] = __nv_bfloat162(h2, h3);
    dl[2 * i]     = __nv_bfloat162(l0, l1);
    dl[2 * i + 1] = __nv_bfloat162(l2, l3);
}

// ---------------------------------------------------------------------------
// prep_w: transpose + split W: g_wt[p][n][k] = split_bf16(W_p[k][n])
// ---------------------------------------------------------------------------
__global__ __launch_bounds__(256) void prep_w(const float* __restrict__ Wq,
                                              const float* __restrict__ Wk,
                                              const float* __restrict__ Wv)
{
    int i = blockIdx.x * 256 + threadIdx.x;   // 0 .. 3*131072-1
    int p   = i >> 17;
    int rem = i & 131071;
    int n = rem >> 10;
    int k = rem & 1023;
    const float* W = (p == 0) ? Wq : (p == 1) ? Wk : Wv;
    float v = W[k * H_SZ + n];
    __nv_bfloat16 h = __float2bfloat16(v);
    __nv_bfloat16 l = __float2bfloat16(v - __bfloat162float(h));
    g_wth[i] = h;
    g_wtl[i] = l;
}

// ---------------------------------------------------------------------------
// proj_tc: q/k/v = x @ W via mma.sync bf16-split. BM=128, BN=128, BK=64.
// 256 threads = 8 warps (warp_m = w>>1 in 0..3, warp_n = w&1).
// Smem rows: 64 bf16 = 128B = 8 chunks of 16B, XOR-swizzled: chunk ^= row&7.
// Epilogue: split-bf16 output (q additionally scaled by 1/32).
// ---------------------------------------------------------------------------
#define PROJ_SMEM 65536

__global__ __launch_bounds__(256) void proj_tc()
{
    extern __shared__ __align__(128) char smem[];
    const uint32_t sb  = smem_u32(smem);
    const uint32_t sAh = sb;
    const uint32_t sAl = sb + 16384;
    const uint32_t sBh = sb + 32768;
    const uint32_t sBl = sb + 49152;

    const int tid  = threadIdx.x;
    const int warp = tid >> 5;
    const int lane = tid & 31;
    const int warp_m = warp >> 1;
    const int warp_n = warp & 1;
    const int row0 = blockIdx.x * 128;
    const int p    = blockIdx.y;

    const __nv_bfloat16* wth = g_wth + (size_t)p * H_SZ * C_SZ;
    const __nv_bfloat16* wtl = g_wtl + (size_t)p * H_SZ * C_SZ;

    float D[2][8][4];
#pragma unroll
    for (int i = 0; i < 2; i++)
#pragma unroll
        for (int j = 0; j < 8; j++)
#pragma unroll
            for (int e = 0; e < 4; e++) D[i][j][e] = 0.0f;

    for (int c = 0; c < 16; c++) {
        const int k0 = c * 64;
        if (c > 0) __syncthreads();
        // Stage A (x) and B (W^T) tiles: 128 rows x 8 chunks each, 4 arrays.
#pragma unroll
        for (int it = 0; it < 4; it++) {
            int idx = it * 256 + tid;       // 0..1023
            int row = idx >> 3;
            int ch  = idx & 7;
            uint32_t soff = (uint32_t)(row * 128 + ((ch ^ (row & 7)) << 4));
            size_t ga = (size_t)(row0 + row) * C_SZ + k0 + ch * 8;
            *(uint4*)(smem + soff)         = *(const uint4*)&g_xh[ga];
            *(uint4*)(smem + 16384 + soff) = *(const uint4*)&g_xl[ga];
            size_t gw = (size_t)row * C_SZ + k0 + ch * 8;   // row == n
            *(uint4*)(smem + 32768 + soff) = *(const uint4*)&wth[gw];
            *(uint4*)(smem + 49152 + soff) = *(const uint4*)&wtl[gw];
        }
        __syncthreads();

#pragma unroll
        for (int ks = 0; ks < 4; ks++) {
            const int ch0 = ks * 2;
            uint32_t ah[2][4], al[2][4];
#pragma unroll
            for (int mf = 0; mf < 2; mf++) {
                int row = warp_m * 32 + mf * 16 + (lane & 15);
                int ch  = ch0 + (lane >> 4);
                uint32_t off = (uint32_t)(row * 128 + ((ch ^ (row & 7)) << 4));
                ldsm4(ah[mf], sAh + off);
                ldsm4(al[mf], sAl + off);
            }
#pragma unroll
            for (int np = 0; np < 4; np++) {
                int nrow = warp_n * 64 + np * 16 + (lane & 7) + ((lane >> 4) << 3);
                int ch   = ch0 + ((lane >> 3) & 1);
                uint32_t off = (uint32_t)(nrow * 128 + ((ch ^ (nrow & 7)) << 4));
                uint32_t bh[4], bl[4];
                ldsm4(bh, sBh + off);
                ldsm4(bl, sBl + off);
#pragma unroll
                for (int mf = 0; mf < 2; mf++) {
                    mma16816(D[mf][2 * np],     ah[mf], bh[0], bh[1]);
                    mma16816(D[mf][2 * np],     al[mf], bh[0], bh[1]);
                    mma16816(D[mf][2 * np],     ah[mf], bl[0], bl[1]);
                    mma16816(D[mf][2 * np + 1], ah[mf], bh[2], bh[3]);
                    mma16816(D[mf][2 * np + 1], al[mf], bh[2], bh[3]);
                    mma16816(D[mf][2 * np + 1], ah[mf], bl[2], bl[3]);
                }
            }
        }
    }

    // Epilogue: split-bf16 store to g_{q,k,v}{h,l}
    __nv_bfloat16* dh = (p == 0) ? g_qh : (p == 1) ? g_kh : g_vh;
    __nv_bfloat16* dl = (p == 0) ? g_ql : (p == 1) ? g_kl : g_vl;
    const float sc = (p == 0) ? SCALE : 1.0f;
    const int gid = lane >> 2;
    const int cb  = 2 * (lane & 3);
#pragma unroll
    for (int mf = 0; mf < 2; mf++) {
        int r0 = row0 + warp_m * 32 + mf * 16 + gid;
        int r1 = r0 + 8;
#pragma unroll
        for (int nf = 0; nf < 8; nf++) {
            int col = warp_n * 64 + nf * 8 + cb;
            float v0 = D[mf][nf][0] * sc, v1 = D[mf][nf][1] * sc;
            float v2 = D[mf][nf][2] * sc, v3 = D[mf][nf][3] * sc;
            uint32_t u0 = __float_as_uint(v0), u1 = __float_as_uint(v1);
            uint32_t u2 = __float_as_uint(v2), u3 = __float_as_uint(v3);
            uint32_t h01 = __byte_perm(u0, u1, 0x7632);
            uint32_t h23 = __byte_perm(u2, u3, 0x7632);
            float l0 = v0 - __uint_as_float(u0 & 0xffff0000u);
            float l1 = v1 - __uint_as_float(u1 & 0xffff0000u);
            float l2 = v2 - __uint_as_float(u2 & 0xffff0000u);
            float l3 = v3 - __uint_as_float(u3 & 0xffff0000u);
            *(uint32_t*)&dh[(size_t)r0 * H_SZ + col] = h01;
            *(uint32_t*)&dh[(size_t)r1 * H_SZ + col] = h23;
            *(uint32_t*)&dl[(size_t)r0 * H_SZ + col] = pack_bf16(l0, l1);
            *(uint32_t*)&dl[(size_t)r1 * H_SZ + col] = pack_bf16(l2, l3);
        }
    }
}

// ---------------------------------------------------------------------------
// attn_tc: flash attention via mma.sync bf16-split.
// CTA = 128 threads (4 warps), BQ = 64 (warp owns m16), CK = 64.
// Each CTA runs two q-tiles: (ip) and (31-ip) of one batch -> exactly 33
// key-chunks per CTA (perfect balance). 128 CTAs total.
// Smem rows: 128 bf16 = 256B = 16 chunks of 16B, swizzle chunk ^= row&7.
// ---------------------------------------------------------------------------
#define AT_SMEM 98304

__global__ __launch_bounds__(128) void attn_tc(float* __restrict__ out)
{
    extern __shared__ __align__(128) char smem[];
    const uint32_t sb  = smem_u32(smem);
    const uint32_t sQh = sb;
    const uint32_t sQl = sb + 16384;
    const uint32_t sKh = sb + 32768;
    const uint32_t sKl = sb + 49152;
    const uint32_t sVh = sb + 65536;
    const uint32_t sVl = sb + 81920;

    const int tid  = threadIdx.x;
    const int warp = tid >> 5;
    const int lane = tid & 31;
    const int gid  = lane >> 2;
    const int cb   = 2 * (lane & 3);
    const int b    = blockIdx.x >> 4;
    const int ip   = blockIdx.x & 15;

    const size_t bbase = (size_t)b * T_SZ * H_SZ;

    for (int pass = 0; pass < 2; pass++) {
        const int tile = pass ? (31 - ip) : ip;
        const int t0 = tile * 64;
        const int nchunks = tile + 1;

        __syncthreads();   // previous pass readers done before Q overwrite
        // Load Q tile (64 x 16 chunks, hi+lo)
#pragma unroll
        for (int it = 0; it < 8; it++) {
            int idx = it * 128 + tid;
            int row = idx >> 4;
            int ch  = idx & 15;
            uint32_t soff = (uint32_t)(row * 256 + ((ch ^ (row & 7)) << 4));
            size_t g = bbase + (size_t)(t0 + row) * H_SZ + ch * 8;
            *(uint4*)(smem + soff)         = *(const uint4*)&g_qh[g];
            *(uint4*)(smem + 16384 + soff) = *(const uint4*)&g_ql[g];
        }

        float O[16][4];
#pragma unroll
        for (int i = 0; i < 16; i++)
#pragma unroll
            for (int e = 0; e < 4; e++) O[i][e] = 0.0f;
        float mr0 = -1e30f, mr1 = -1e30f, lr0 = 0.0f, lr1 = 0.0f;

        for (int c = 0; c < nchunks; c++) {
            const int s0 = c * 64;
            __syncthreads();   // smem K/V reuse + Q store visibility
            // Load K,V chunk (hi+lo): 64 x 16 chunks each
#pragma unroll
            for (int it = 0; it < 8; it++) {
                int idx = it * 128 + tid;
                int row = idx >> 4;
                int ch  = idx & 15;
                uint32_t soff = (uint32_t)(row * 256 + ((ch ^ (row & 7)) << 4));
                size_t g = bbase + (size_t)(s0 + row) * H_SZ + ch * 8;
                *(uint4*)(smem + 32768 + soff) = *(const uint4*)&g_kh[g];
                *(uint4*)(smem + 49152 + soff) = *(const uint4*)&g_kl[g];
                *(uint4*)(smem + 65536 + soff) = *(const uint4*)&g_vh[g];
                *(uint4*)(smem + 81920 + soff) = *(const uint4*)&g_vl[g];
            }
            __syncthreads();

            // ---- S = Q K^T (split: QhKh + QlKh + QhKl) ----
            float S[8][4];
#pragma unroll
            for (int i = 0; i < 8; i++)
#pragma unroll
                for (int e = 0; e < 4; e++) S[i][e] = 0.0f;

#pragma unroll
            for (int kf = 0; kf < 8; kf++) {
                const int ch0 = kf * 2;
                uint32_t ah[4], al[4];
                {
                    int row = warp * 16 + (lane & 15);
                    int ch  = ch0 + (lane >> 4);
                    uint32_t off = (uint32_t)(row * 256 + ((ch ^ (row & 7)) << 4));
                    ldsm4(ah, sQh + off);
                    ldsm4(al, sQl + off);
                }
#pragma unroll
                for (int np = 0; np < 4; np++) {
                    int nrow = np * 16 + (lane & 7) + ((lane >> 4) << 3);
                    int ch   = ch0 + ((lane >> 3) & 1);
                    uint32_t off = (uint32_t)(nrow * 256 + ((ch ^ (nrow & 7)) << 4));
                    uint32_t bh[4], bl[4];
                    ldsm4(bh, sKh + off);
                    ldsm4(bl, sKl + off);
                    mma16816(S[2 * np],     ah, bh[0], bh[1]);
                    mma16816(S[2 * np],     al, bh[0], bh[1]);
                    mma16816(S[2 * np],     ah, bl[0], bl[1]);
                    mma16816(S[2 * np + 1], ah, bh[2], bh[3]);
                    mma16816(S[2 * np + 1], al, bh[2], bh[3]);
                    mma16816(S[2 * np + 1], ah, bl[2], bl[3]);
                }
            }

            // ---- causal mask (only final chunk is diagonal: s0 == t0) ----
            if (c == nchunks - 1) {
                int r0 = warp * 16 + gid;
#pragma unroll
                for (int nf = 0; nf < 8; nf++) {
                    int j0 = nf * 8 + cb;
                    if (j0     > r0)     S[nf][0] = -1e30f;
                    if (j0 + 1 > r0)     S[nf][1] = -1e30f;
                    if (j0     > r0 + 8) S[nf][2] = -1e30f;
                    if (j0 + 1 > r0 + 8) S[nf][3] = -1e30f;
                }
            }

            // ---- online softmax ----
            float mx0 = mr0, mx1 = mr1;
#pragma unroll
            for (int nf = 0; nf < 8; nf++) {
                mx0 = fmaxf(mx0, fmaxf(S[nf][0], S[nf][1]));
                mx1 = fmaxf(mx1, fmaxf(S[nf][2], S[nf][3]));
            }
            mx0 = fmaxf(mx0, __shfl_xor_sync(0xffffffffu, mx0, 1));
            mx0 = fmaxf(mx0, __shfl_xor_sync(0xffffffffu, mx0, 2));
            mx1 = fmaxf(mx1, __shfl_xor_sync(0xffffffffu, mx1, 1));
            mx1 = fmaxf(mx1, __shfl_xor_sync(0xffffffffu, mx1, 2));
            float corr0 = __expf(mr0 - mx0);
            float corr1 = __expf(mr1 - mx1);
            float sum0 = 0.0f, sum1 = 0.0f;
#pragma unroll
            for (int nf = 0; nf < 8; nf++) {
                S[nf][0] = __expf(S[nf][0] - mx0); sum0 += S[nf][0];
                S[nf][1] = __expf(S[nf][1] - mx0); sum0 += S[nf][1];
                S[nf][2] = __expf(S[nf][2] - mx1); sum1 += S[nf][2];
                S[nf][3] = __expf(S[nf][3] - mx1); sum1 += S[nf][3];
            }
            sum0 += __shfl_xor_sync(0xffffffffu, sum0, 1);
            sum0 += __shfl_xor_sync(0xffffffffu, sum0, 2);
            sum1 += __shfl_xor_sync(0xffffffffu, sum1, 1);
            sum1 += __shfl_xor_sync(0xffffffffu, sum1, 2);
            lr0 = lr0 * corr0 + sum0;  mr0 = mx0;
            lr1 = lr1 * corr1 + sum1;  mr1 = mx1;
#pragma unroll
            for (int nf = 0; nf < 16; nf++) {
                O[nf][0] *= corr0; O[nf][1] *= corr0;
                O[nf][2] *= corr1; O[nf][3] *= corr1;
            }

            // ---- O += P V (split: PhVh + PlVh + PhVl) ----
#pragma unroll
            for (int kf = 0; kf < 4; kf++) {
                uint32_t ph[4], pl[4];
                {
                    float s00 = S[2*kf][0],   s01 = S[2*kf][1];
                    float s02 = S[2*kf][2],   s03 = S[2*kf][3];
                    float s10 = S[2*kf+1][0], s11 = S[2*kf+1][1];
                    float s12 = S[2*kf+1][2], s13 = S[2*kf+1][3];
                    uint32_t u00 = __float_as_uint(s00), u01 = __float_as_uint(s01);
                    uint32_t u02 = __float_as_uint(s02), u03 = __float_as_uint(s03);
                    uint32_t u10 = __float_as_uint(s10), u11 = __float_as_uint(s11);
                    uint32_t u12 = __float_as_uint(s12), u13 = __float_as_uint(s13);
                    ph[0] = __byte_perm(u00, u01, 0x7632);
                    ph[1] = __byte_perm(u02, u03, 0x7632);
                    ph[2] = __byte_perm(u10, u11, 0x7632);
                    ph[3] = __byte_perm(u12, u13, 0x7632);
                    pl[0] = pack_bf16(s00 - __uint_as_float(u00 & 0xffff0000u),
                                      s01 - __uint_as_float(u01 & 0xffff0000u));
                    pl[1] = pack_bf16(s02 - __uint_as_float(u02 & 0xffff0000u),
                                      s03 - __uint_as_float(u03 & 0xffff0000u));
                    pl[2] = pack_bf16(s10 - __uint_as_float(u10 & 0xffff0000u),
                                      s11 - __uint_as_float(u11 & 0xffff0000u));
                    pl[3] = pack_bf16(s12 - __uint_as_float(u12 & 0xffff0000u),
                                      s13 - __uint_as_float(u13 & 0xffff0000u));
                }
#pragma unroll
                for (int np = 0; np < 8; np++) {
                    int row = kf * 16 + (lane & 7) + (((lane >> 3) & 1) << 3);
                    int ch  = np * 2 + (lane >> 4);
                    uint32_t off = (uint32_t)(row * 256 + ((ch ^ (row & 7)) << 4));
                    uint32_t vh[4], vl[4];
                    ldsm4t(vh, sVh + off);
                    ldsm4t(vl, sVl + off);
                    mma16816(O[2 * np],     ph, vh[0], vh[1]);
                    mma16816(O[2 * np],     pl, vh[0], vh[1]);
                    mma16816(O[2 * np],     ph, vl[0], vl[1]);
                    mma16816(O[2 * np + 1], ph, vh[2], vh[3]);
                    mma16816(O[2 * np + 1], pl, vh[2], vh[3]);
                    mma16816(O[2 * np + 1], ph, vl[2], vl[3]);
                }
            }
        }

        // ---- finalize + store ----
        float inv0 = 1.0f / lr0;
        float inv1 = 1.0f / lr1;
        size_t rg0 = (size_t)b * T_SZ + t0 + warp * 16 + gid;
        size_t rg1 = rg0 + 8;
#pragma unroll
        for (int nf = 0; nf < 16; nf++) {
            int col = nf * 8 + cb;
            float2 v0 = make_float2(O[nf][0] * inv0, O[nf][1] * inv0);
            float2 v1 = make_float2(O[nf][2] * inv1, O[nf][3] * inv1);
            *(float2*)&out[rg0 * H_SZ + col] = v0;
            *(float2*)&out[rg1 * H_SZ + col] = v1;
        }
    }
}

// ---------------------------------------------------------------------------
extern "C" void kernel_launch(void* const* d_in, const int* in_sizes, int n_in,
                              void* d_out, int out_size)
{
    const float* x  = (const float*)d_in[0];   // [8,2048,1024]
    const float* Wq = (const float*)d_in[1];   // [1024,128]
    const float* Wk = (const float*)d_in[2];
    const float* Wv = (const float*)d_in[3];
    float* out = (float*)d_out;                // [8,2048,128]

    cudaFuncSetAttribute(proj_tc, cudaFuncAttributeMaxDynamicSharedMemorySize,
                         PROJ_SMEM);
    cudaFuncSetAttribute(attn_tc, cudaFuncAttributeMaxDynamicSharedMemorySize,
                         AT_SMEM);

    prep_x<<<(ROWS * C_SZ / 4) / 256, 256>>>(x);
    prep_w<<<(3 * H_SZ * C_SZ) / 256, 256>>>(Wq, Wk, Wv);
    proj_tc<<<dim3(ROWS / 128, 3), 256, PROJ_SMEM>>>();
    attn_tc<<<128, 128, AT_SMEM>>>(out);
}

// round 7
// speedup vs baseline: 4.5861x; 1.1396x over previous
#include <cuda_runtime.h>
#include <cuda_bf16.h>
#include <cstdint>

// Problem constants
#define B_SZ   8
#define T_SZ   2048
#define C_SZ   1024
#define H_SZ   128
#define ROWS   (B_SZ * T_SZ)       // 16384
#define SCALE  (0.03125f)          // C^-0.5 = 1/32

// Scratch (device statics: allocation-free rule)
__device__ __nv_bfloat16 g_wth[3 * H_SZ * C_SZ];   // W^T split: [proj][n][k]
__device__ __nv_bfloat16 g_wtl[3 * H_SZ * C_SZ];
__device__ __nv_bfloat16 g_qh[ROWS * H_SZ];        // q scaled by 1/32, split
__device__ __nv_bfloat16 g_ql[ROWS * H_SZ];
__device__ __nv_bfloat16 g_kh[ROWS * H_SZ];
__device__ __nv_bfloat16 g_kl[ROWS * H_SZ];
__device__ __nv_bfloat16 g_vh[ROWS * H_SZ];
__device__ __nv_bfloat16 g_vl[ROWS * H_SZ];

// ---------------------------------------------------------------------------
// Helpers: mma.sync (sm_80+ PTX; valid under compute_103) + ldmatrix + cp.async
// ---------------------------------------------------------------------------
__device__ __forceinline__ uint32_t smem_u32(const void* p) {
    uint32_t a;
    asm("{ .reg .u64 t; cvta.to.shared.u64 t, %1; cvt.u32.u64 %0, t; }"
        : "=r"(a) : "l"(p));
    return a;
}
__device__ __forceinline__ void ldsm4(uint32_t* r, uint32_t addr) {
    asm volatile("ldmatrix.sync.aligned.m8n8.x4.shared.b16 {%0,%1,%2,%3}, [%4];"
                 : "=r"(r[0]), "=r"(r[1]), "=r"(r[2]), "=r"(r[3]) : "r"(addr));
}
__device__ __forceinline__ void ldsm4t(uint32_t* r, uint32_t addr) {
    asm volatile("ldmatrix.sync.aligned.m8n8.x4.trans.shared.b16 {%0,%1,%2,%3}, [%4];"
                 : "=r"(r[0]), "=r"(r[1]), "=r"(r[2]), "=r"(r[3]) : "r"(addr));
}
__device__ __forceinline__ void mma16816(float* d, const uint32_t* a,
                                         uint32_t b0, uint32_t b1) {
    asm volatile(
        "mma.sync.aligned.m16n8k16.row.col.f32.bf16.bf16.f32 "
        "{%0,%1,%2,%3}, {%4,%5,%6,%7}, {%8,%9}, {%0,%1,%2,%3};"
        : "+f"(d[0]), "+f"(d[1]), "+f"(d[2]), "+f"(d[3])
        : "r"(a[0]), "r"(a[1]), "r"(a[2]), "r"(a[3]), "r"(b0), "r"(b1));
}
// pack two fp32 -> bf16x2 (lo in low half)
__device__ __forceinline__ uint32_t pack_bf16(float lo, float hi) {
    uint32_t r;
    asm("cvt.rn.bf16x2.f32 %0, %1, %2;" : "=r"(r) : "f"(hi), "f"(lo));
    return r;
}
__device__ __forceinline__ void cp16(uint32_t dst, const void* src) {
    asm volatile("cp.async.cg.shared.global [%0], [%1], 16;"
                 :: "r"(dst), "l"(src));
}
#define CP_COMMIT() asm volatile("cp.async.commit_group;" ::: "memory")
#define CP_WAIT0()  asm volatile("cp.async.wait_group 0;" ::: "memory")

// ---------------------------------------------------------------------------
// prep_w: transpose + split W: g_wt[p][n][k] = split_bf16(W_p[k][n])
// ---------------------------------------------------------------------------
__global__ __launch_bounds__(256) void prep_w(const float* __restrict__ Wq,
                                              const float* __restrict__ Wk,
                                              const float* __restrict__ Wv)
{
    int i = blockIdx.x * 256 + threadIdx.x;   // 0 .. 3*131072-1
    int p   = i >> 17;
    int rem = i & 131071;
    int n = rem >> 10;
    int k = rem & 1023;
    const float* W = (p == 0) ? Wq : (p == 1) ? Wk : Wv;
    float v = W[k * H_SZ + n];
    __nv_bfloat16 h = __float2bfloat16(v);
    __nv_bfloat16 l = __float2bfloat16(v - __bfloat162float(h));
    g_wth[i] = h;
    g_wtl[i] = l;
}

// ---------------------------------------------------------------------------
// proj_tc: q/k/v = x @ W via mma.sync bf16-split. BM=128, BN=128, BK=64.
// Grid (3, 128): blockIdx.x = projection (adjacent bids share x slab -> L2),
// blockIdx.y = row slab. 256 threads = 8 warps. x is split fp32->bf16 hi/lo
// during staging (prep_x fused away). B tiles staged via cp.async.
// Smem rows: 64 bf16 = 128B = 8 chunks of 16B, XOR-swizzled: chunk ^= row&7.
// ---------------------------------------------------------------------------
#define PROJ_SMEM 65536

__global__ __launch_bounds__(256, 2) void proj_tc(const float* __restrict__ x)
{
    extern __shared__ __align__(128) char smem[];
    const uint32_t sb  = smem_u32(smem);
    const uint32_t sAh = sb;
    const uint32_t sAl = sb + 16384;
    const uint32_t sBh = sb + 32768;
    const uint32_t sBl = sb + 49152;

    const int tid  = threadIdx.x;
    const int warp = tid >> 5;
    const int lane = tid & 31;
    const int warp_m = warp >> 1;
    const int warp_n = warp & 1;
    const int p    = blockIdx.x;
    const int row0 = blockIdx.y * 128;

    const __nv_bfloat16* wth = g_wth + (size_t)p * H_SZ * C_SZ;
    const __nv_bfloat16* wtl = g_wtl + (size_t)p * H_SZ * C_SZ;

    float D[2][8][4];
#pragma unroll
    for (int i = 0; i < 2; i++)
#pragma unroll
        for (int j = 0; j < 8; j++)
#pragma unroll
            for (int e = 0; e < 4; e++) D[i][j][e] = 0.0f;

    for (int c = 0; c < 16; c++) {
        const int k0 = c * 64;
        if (c > 0) __syncthreads();
        // B tiles (already split bf16): cp.async, 4 x 16B per thread per array
#pragma unroll
        for (int it = 0; it < 4; it++) {
            int idx = it * 256 + tid;       // 0..1023
            int row = idx >> 3;
            int ch  = idx & 7;
            uint32_t soff = (uint32_t)(row * 128 + ((ch ^ (row & 7)) << 4));
            size_t gw = (size_t)row * C_SZ + k0 + ch * 8;   // row == n
            cp16(sBh + soff, &wth[gw]);
            cp16(sBl + soff, &wtl[gw]);
        }
        CP_COMMIT();
        // A tile: load fp32 x, split to bf16 hi/lo in registers, STS 8B each.
        // 2048 float4 per tile -> 8 per thread. hc = half-chunk (8B) 0..15.
#pragma unroll
        for (int it = 0; it < 8; it++) {
            int idx = it * 256 + tid;       // 0..2047
            int row = idx >> 4;
            int hc  = idx & 15;
            int ch  = hc >> 1;
            uint32_t soff = (uint32_t)(row * 128 + ((ch ^ (row & 7)) << 4)
                                       + (hc & 1) * 8);
            float4 v = *(const float4*)&x[(size_t)(row0 + row) * C_SZ + k0 + hc * 4];
            __nv_bfloat16 h0 = __float2bfloat16(v.x);
            __nv_bfloat16 h1 = __float2bfloat16(v.y);
            __nv_bfloat16 h2 = __float2bfloat16(v.z);
            __nv_bfloat16 h3 = __float2bfloat16(v.w);
            uint32_t hi01 = __float_as_uint(0.0f);  // placate compiler
            (void)hi01;
            __nv_bfloat162 hp0(h0, h1), hp1(h2, h3);
            *(uint2*)(smem + soff) =
                make_uint2(*(uint32_t*)&hp0, *(uint32_t*)&hp1);
            float l0 = v.x - __bfloat162float(h0);
            float l1 = v.y - __bfloat162float(h1);
            float l2 = v.z - __bfloat162float(h2);
            float l3 = v.w - __bfloat162float(h3);
            *(uint2*)(smem + 16384 + soff) =
                make_uint2(pack_bf16(l0, l1), pack_bf16(l2, l3));
        }
        CP_WAIT0();
        __syncthreads();

#pragma unroll
        for (int ks = 0; ks < 4; ks++) {
            const int ch0 = ks * 2;
            uint32_t ah[2][4], al[2][4];
#pragma unroll
            for (int mf = 0; mf < 2; mf++) {
                int row = warp_m * 32 + mf * 16 + (lane & 15);
                int ch  = ch0 + (lane >> 4);
                uint32_t off = (uint32_t)(row * 128 + ((ch ^ (row & 7)) << 4));
                ldsm4(ah[mf], sAh + off);
                ldsm4(al[mf], sAl + off);
            }
#pragma unroll
            for (int np = 0; np < 4; np++) {
                int nrow = warp_n * 64 + np * 16 + (lane & 7) + ((lane >> 4) << 3);
                int ch   = ch0 + ((lane >> 3) & 1);
                uint32_t off = (uint32_t)(nrow * 128 + ((ch ^ (nrow & 7)) << 4));
                uint32_t bh[4], bl[4];
                ldsm4(bh, sBh + off);
                ldsm4(bl, sBl + off);
#pragma unroll
                for (int mf = 0; mf < 2; mf++) {
                    mma16816(D[mf][2 * np],     ah[mf], bh[0], bh[1]);
                    mma16816(D[mf][2 * np],     al[mf], bh[0], bh[1]);
                    mma16816(D[mf][2 * np],     ah[mf], bl[0], bl[1]);
                    mma16816(D[mf][2 * np + 1], ah[mf], bh[2], bh[3]);
                    mma16816(D[mf][2 * np + 1], al[mf], bh[2], bh[3]);
                    mma16816(D[mf][2 * np + 1], ah[mf], bl[2], bl[3]);
                }
            }
        }
    }

    // Epilogue: split-bf16 store to g_{q,k,v}{h,l}
    __nv_bfloat16* dh = (p == 0) ? g_qh : (p == 1) ? g_kh : g_vh;
    __nv_bfloat16* dl = (p == 0) ? g_ql : (p == 1) ? g_kl : g_vl;
    const float sc = (p == 0) ? SCALE : 1.0f;
    const int gid = lane >> 2;
    const int cb  = 2 * (lane & 3);
#pragma unroll
    for (int mf = 0; mf < 2; mf++) {
        int r0 = row0 + warp_m * 32 + mf * 16 + gid;
        int r1 = r0 + 8;
#pragma unroll
        for (int nf = 0; nf < 8; nf++) {
            int col = warp_n * 64 + nf * 8 + cb;
            float v0 = D[mf][nf][0] * sc, v1 = D[mf][nf][1] * sc;
            float v2 = D[mf][nf][2] * sc, v3 = D[mf][nf][3] * sc;
            uint32_t u0 = __float_as_uint(v0), u1 = __float_as_uint(v1);
            uint32_t u2 = __float_as_uint(v2), u3 = __float_as_uint(v3);
            uint32_t h01 = __byte_perm(u0, u1, 0x7632);
            uint32_t h23 = __byte_perm(u2, u3, 0x7632);
            float l0 = v0 - __uint_as_float(u0 & 0xffff0000u);
            float l1 = v1 - __uint_as_float(u1 & 0xffff0000u);
            float l2 = v2 - __uint_as_float(u2 & 0xffff0000u);
            float l3 = v3 - __uint_as_float(u3 & 0xffff0000u);
            *(uint32_t*)&dh[(size_t)r0 * H_SZ + col] = h01;
            *(uint32_t*)&dh[(size_t)r1 * H_SZ + col] = h23;
            *(uint32_t*)&dl[(size_t)r0 * H_SZ + col] = pack_bf16(l0, l1);
            *(uint32_t*)&dl[(size_t)r1 * H_SZ + col] = pack_bf16(l2, l3);
        }
    }
}

// ---------------------------------------------------------------------------
// attn_tc: flash attention via mma.sync bf16-split.
// One 64-row q-tile per CTA, 128 threads (4 warps, warp owns m16), CK=64.
// Grid 256, weight-aware schedule: bid and bid+148 share an SM (2 CTAs/SM),
// so heavy tiles (desc) for bid<148 pair with light tiles (asc) above.
// cp.async staging. Smem rows: 128 bf16 = 256B = 16 chunks, chunk ^= row&7.
// ---------------------------------------------------------------------------
#define AT_SMEM 98304

__global__ __launch_bounds__(128, 2) void attn_tc(float* __restrict__ out)
{
    extern __shared__ __align__(128) char smem[];
    const uint32_t sb  = smem_u32(smem);
    const uint32_t sQh = sb;
    const uint32_t sQl = sb + 16384;
    const uint32_t sKh = sb + 32768;
    const uint32_t sKl = sb + 49152;
    const uint32_t sVh = sb + 65536;
    const uint32_t sVl = sb + 81920;

    const int tid  = threadIdx.x;
    const int warp = tid >> 5;
    const int lane = tid & 31;
    const int gid  = lane >> 2;
    const int cb   = 2 * (lane & 3);

    const int bid  = blockIdx.x;
    const int rank = (bid < 148) ? bid : 403 - bid;
    const int tile = 31 - (rank >> 3);
    const int b    = rank & 7;
    const int t0   = tile * 64;
    const int nchunks = tile + 1;

    const size_t bbase = (size_t)b * T_SZ * H_SZ;

    // Stage Q tile (hi+lo) via cp.async (committed with chunk 0's group)
#pragma unroll
    for (int it = 0; it < 8; it++) {
        int idx = it * 128 + tid;
        int row = idx >> 4;
        int ch  = idx & 15;
        uint32_t soff = (uint32_t)(row * 256 + ((ch ^ (row & 7)) << 4));
        size_t g = bbase + (size_t)(t0 + row) * H_SZ + ch * 8;
        cp16(sQh + soff, &g_qh[g]);
        cp16(sQl + soff, &g_ql[g]);
    }

    float O[16][4];
#pragma unroll
    for (int i = 0; i < 16; i++)
#pragma unroll
        for (int e = 0; e < 4; e++) O[i][e] = 0.0f;
    float mr0 = -1e30f, mr1 = -1e30f, lr0 = 0.0f, lr1 = 0.0f;

    for (int c = 0; c < nchunks; c++) {
        const int s0 = c * 64;
        __syncthreads();   // smem K/V reuse guard
        // Stage K,V chunk (hi+lo) via cp.async
#pragma unroll
        for (int it = 0; it < 8; it++) {
            int idx = it * 128 + tid;
            int row = idx >> 4;
            int ch  = idx & 15;
            uint32_t soff = (uint32_t)(row * 256 + ((ch ^ (row & 7)) << 4));
            size_t g = bbase + (size_t)(s0 + row) * H_SZ + ch * 8;
            cp16(sKh + soff, &g_kh[g]);
            cp16(sKl + soff, &g_kl[g]);
            cp16(sVh + soff, &g_vh[g]);
            cp16(sVl + soff, &g_vl[g]);
        }
        CP_COMMIT();
        CP_WAIT0();
        __syncthreads();

        // ---- S = Q K^T (split: QhKh + QlKh + QhKl) ----
        float S[8][4];
#pragma unroll
        for (int i = 0; i < 8; i++)
#pragma unroll
            for (int e = 0; e < 4; e++) S[i][e] = 0.0f;

#pragma unroll
        for (int kf = 0; kf < 8; kf++) {
            const int ch0 = kf * 2;
            uint32_t ah[4], al[4];
            {
                int row = warp * 16 + (lane & 15);
                int ch  = ch0 + (lane >> 4);
                uint32_t off = (uint32_t)(row * 256 + ((ch ^ (row & 7)) << 4));
                ldsm4(ah, sQh + off);
                ldsm4(al, sQl + off);
            }
#pragma unroll
            for (int np = 0; np < 4; np++) {
                int nrow = np * 16 + (lane & 7) + ((lane >> 4) << 3);
                int ch   = ch0 + ((lane >> 3) & 1);
                uint32_t off = (uint32_t)(nrow * 256 + ((ch ^ (nrow & 7)) << 4));
                uint32_t bh[4], bl[4];
                ldsm4(bh, sKh + off);
                ldsm4(bl, sKl + off);
                mma16816(S[2 * np],     ah, bh[0], bh[1]);
                mma16816(S[2 * np],     al, bh[0], bh[1]);
                mma16816(S[2 * np],     ah, bl[0], bl[1]);
                mma16816(S[2 * np + 1], ah, bh[2], bh[3]);
                mma16816(S[2 * np + 1], al, bh[2], bh[3]);
                mma16816(S[2 * np + 1], ah, bl[2], bl[3]);
            }
        }

        // ---- causal mask (only final chunk is diagonal: s0 == t0) ----
        if (c == nchunks - 1) {
            int r0 = warp * 16 + gid;
#pragma unroll
            for (int nf = 0; nf < 8; nf++) {
                int j0 = nf * 8 + cb;
                if (j0     > r0)     S[nf][0] = -1e30f;
                if (j0 + 1 > r0)     S[nf][1] = -1e30f;
                if (j0     > r0 + 8) S[nf][2] = -1e30f;
                if (j0 + 1 > r0 + 8) S[nf][3] = -1e30f;
            }
        }

        // ---- online softmax ----
        float mx0 = mr0, mx1 = mr1;
#pragma unroll
        for (int nf = 0; nf < 8; nf++) {
            mx0 = fmaxf(mx0, fmaxf(S[nf][0], S[nf][1]));
            mx1 = fmaxf(mx1, fmaxf(S[nf][2], S[nf][3]));
        }
        mx0 = fmaxf(mx0, __shfl_xor_sync(0xffffffffu, mx0, 1));
        mx0 = fmaxf(mx0, __shfl_xor_sync(0xffffffffu, mx0, 2));
        mx1 = fmaxf(mx1, __shfl_xor_sync(0xffffffffu, mx1, 1));
        mx1 = fmaxf(mx1, __shfl_xor_sync(0xffffffffu, mx1, 2));
        float corr0 = __expf(mr0 - mx0);
        float corr1 = __expf(mr1 - mx1);
        float sum0 = 0.0f, sum1 = 0.0f;
#pragma unroll
        for (int nf = 0; nf < 8; nf++) {
            S[nf][0] = __expf(S[nf][0] - mx0); sum0 += S[nf][0];
            S[nf][1] = __expf(S[nf][1] - mx0); sum0 += S[nf][1];
            S[nf][2] = __expf(S[nf][2] - mx1); sum1 += S[nf][2];
            S[nf][3] = __expf(S[nf][3] - mx1); sum1 += S[nf][3];
        }
        sum0 += __shfl_xor_sync(0xffffffffu, sum0, 1);
        sum0 += __shfl_xor_sync(0xffffffffu, sum0, 2);
        sum1 += __shfl_xor_sync(0xffffffffu, sum1, 1);
        sum1 += __shfl_xor_sync(0xffffffffu, sum1, 2);
        lr0 = lr0 * corr0 + sum0;  mr0 = mx0;
        lr1 = lr1 * corr1 + sum1;  mr1 = mx1;
#pragma unroll
        for (int nf = 0; nf < 16; nf++) {
            O[nf][0] *= corr0; O[nf][1] *= corr0;
            O[nf][2] *= corr1; O[nf][3] *= corr1;
        }

        // ---- O += P V (split: PhVh + PlVh + PhVl) ----
#pragma unroll
        for (int kf = 0; kf < 4; kf++) {
            uint32_t ph[4], pl[4];
            {
                float s00 = S[2*kf][0],   s01 = S[2*kf][1];
                float s02 = S[2*kf][2],   s03 = S[2*kf][3];
                float s10 = S[2*kf+1][0], s11 = S[2*kf+1][1];
                float s12 = S[2*kf+1][2], s13 = S[2*kf+1][3];
                uint32_t u00 = __float_as_uint(s00), u01 = __float_as_uint(s01);
                uint32_t u02 = __float_as_uint(s02), u03 = __float_as_uint(s03);
                uint32_t u10 = __float_as_uint(s10), u11 = __float_as_uint(s11);
                uint32_t u12 = __float_as_uint(s12), u13 = __float_as_uint(s13);
                ph[0] = __byte_perm(u00, u01, 0x7632);
                ph[1] = __byte_perm(u02, u03, 0x7632);
                ph[2] = __byte_perm(u10, u11, 0x7632);
                ph[3] = __byte_perm(u12, u13, 0x7632);
                pl[0] = pack_bf16(s00 - __uint_as_float(u00 & 0xffff0000u),
                                  s01 - __uint_as_float(u01 & 0xffff0000u));
                pl[1] = pack_bf16(s02 - __uint_as_float(u02 & 0xffff0000u),
                                  s03 - __uint_as_float(u03 & 0xffff0000u));
                pl[2] = pack_bf16(s10 - __uint_as_float(u10 & 0xffff0000u),
                                  s11 - __uint_as_float(u11 & 0xffff0000u));
                pl[3] = pack_bf16(s12 - __uint_as_float(u12 & 0xffff0000u),
                                  s13 - __uint_as_float(u13 & 0xffff0000u));
            }
#pragma unroll
            for (int np = 0; np < 8; np++) {
                int row = kf * 16 + (lane & 7) + (((lane >> 3) & 1) << 3);
                int ch  = np * 2 + (lane >> 4);
                uint32_t off = (uint32_t)(row * 256 + ((ch ^ (row & 7)) << 4));
                uint32_t vh[4], vl[4];
                ldsm4t(vh, sVh + off);
                ldsm4t(vl, sVl + off);
                mma16816(O[2 * np],     ph, vh[0], vh[1]);
                mma16816(O[2 * np],     pl, vh[0], vh[1]);
                mma16816(O[2 * np],     ph, vl[0], vl[1]);
                mma16816(O[2 * np + 1], ph, vh[2], vh[3]);
                mma16816(O[2 * np + 1], pl, vh[2], vh[3]);
                mma16816(O[2 * np + 1], ph, vl[2], vl[3]);
            }
        }
    }

    // ---- finalize + store ----
    float inv0 = 1.0f / lr0;
    float inv1 = 1.0f / lr1;
    size_t rg0 = (size_t)b * T_SZ + t0 + warp * 16 + gid;
    size_t rg1 = rg0 + 8;
#pragma unroll
    for (int nf = 0; nf < 16; nf++) {
        int col = nf * 8 + cb;
        float2 v0 = make_float2(O[nf][0] * inv0, O[nf][1] * inv0);
        float2 v1 = make_float2(O[nf][2] * inv1, O[nf][3] * inv1);
        *(float2*)&out[rg0 * H_SZ + col] = v0;
        *(float2*)&out[rg1 * H_SZ + col] = v1;
    }
}

// ---------------------------------------------------------------------------
extern "C" void kernel_launch(void* const* d_in, const int* in_sizes, int n_in,
                              void* d_out, int out_size)
{
    const float* x  = (const float*)d_in[0];   // [8,2048,1024]
    const float* Wq = (const float*)d_in[1];   // [1024,128]
    const float* Wk = (const float*)d_in[2];
    const float* Wv = (const float*)d_in[3];
    float* out = (float*)d_out;                // [8,2048,128]

    cudaFuncSetAttribute(proj_tc, cudaFuncAttributeMaxDynamicSharedMemorySize,
                         PROJ_SMEM);
    cudaFuncSetAttribute(attn_tc, cudaFuncAttributeMaxDynamicSharedMemorySize,
                         AT_SMEM);

    prep_w<<<(3 * H_SZ * C_SZ) / 256, 256>>>(Wq, Wk, Wv);
    proj_tc<<<dim3(3, ROWS / 128), 256, PROJ_SMEM>>>(x);
    attn_tc<<<256, 128, AT_SMEM>>>(out);
}

// round 10
// speedup vs baseline: 4.9077x; 1.0701x over previous
#include <cuda_runtime.h>
#include <cuda_bf16.h>
#include <cstdint>

// Problem constants
#define B_SZ   8
#define T_SZ   2048
#define C_SZ   1024
#define H_SZ   128
#define ROWS   (B_SZ * T_SZ)       // 16384
#define SCALE  (0.03125f)          // C^-0.5 = 1/32

// Scratch (device statics: allocation-free rule)
__device__ __nv_bfloat16 g_xh[ROWS * C_SZ];        // split-bf16 of x
__device__ __nv_bfloat16 g_xl[ROWS * C_SZ];
__device__ __nv_bfloat16 g_wth[3 * H_SZ * C_SZ];   // W^T split: [proj][n][k]
__device__ __nv_bfloat16 g_wtl[3 * H_SZ * C_SZ];
__device__ __nv_bfloat16 g_qh[ROWS * H_SZ];        // q scaled by 1/32, split
__device__ __nv_bfloat16 g_ql[ROWS * H_SZ];
__device__ __nv_bfloat16 g_kh[ROWS * H_SZ];
__device__ __nv_bfloat16 g_kl[ROWS * H_SZ];
__device__ __nv_bfloat16 g_vh[ROWS * H_SZ];
__device__ __nv_bfloat16 g_vl[ROWS * H_SZ];

// ---------------------------------------------------------------------------
// Helpers: mma.sync (sm_80+ PTX; valid under compute_103) + ldmatrix + cp.async
// ---------------------------------------------------------------------------
__device__ __forceinline__ uint32_t smem_u32(const void* p) {
    uint32_t a;
    asm("{ .reg .u64 t; cvta.to.shared.u64 t, %1; cvt.u32.u64 %0, t; }"
        : "=r"(a) : "l"(p));
    return a;
}
__device__ __forceinline__ void ldsm4(uint32_t* r, uint32_t addr) {
    asm volatile("ldmatrix.sync.aligned.m8n8.x4.shared.b16 {%0,%1,%2,%3}, [%4];"
                 : "=r"(r[0]), "=r"(r[1]), "=r"(r[2]), "=r"(r[3]) : "r"(addr));
}
__device__ __forceinline__ void ldsm4t(uint32_t* r, uint32_t addr) {
    asm volatile("ldmatrix.sync.aligned.m8n8.x4.trans.shared.b16 {%0,%1,%2,%3}, [%4];"
                 : "=r"(r[0]), "=r"(r[1]), "=r"(r[2]), "=r"(r[3]) : "r"(addr));
}
__device__ __forceinline__ void mma16816(float* d, const uint32_t* a,
                                         uint32_t b0, uint32_t b1) {
    asm volatile(
        "mma.sync.aligned.m16n8k16.row.col.f32.bf16.bf16.f32 "
        "{%0,%1,%2,%3}, {%4,%5,%6,%7}, {%8,%9}, {%0,%1,%2,%3};"
        : "+f"(d[0]), "+f"(d[1]), "+f"(d[2]), "+f"(d[3])
        : "r"(a[0]), "r"(a[1]), "r"(a[2]), "r"(a[3]), "r"(b0), "r"(b1));
}
// pack two fp32 -> bf16x2 (lo in low half)
__device__ __forceinline__ uint32_t pack_bf16(float lo, float hi) {
    uint32_t r;
    asm("cvt.rn.bf16x2.f32 %0, %1, %2;" : "=r"(r) : "f"(hi), "f"(lo));
    return r;
}
__device__ __forceinline__ void cp16(uint32_t dst, const void* src) {
    asm volatile("cp.async.cg.shared.global [%0], [%1], 16;"
                 :: "r"(dst), "l"(src));
}
#define CP_COMMIT() asm volatile("cp.async.commit_group;" ::: "memory")
#define CP_WAIT0()  asm volatile("cp.async.wait_group 0;" ::: "memory")
#define CP_WAIT1()  asm volatile("cp.async.wait_group 1;" ::: "memory")

// ---------------------------------------------------------------------------
// prep_x: split x (fp32) into bf16 hi/lo pair (memory-bound, once)
// ---------------------------------------------------------------------------
__global__ __launch_bounds__(256) void prep_x(const float* __restrict__ x)
{
    size_t i = (size_t)blockIdx.x * 256 + threadIdx.x;   // float4 index
    float4 v = ((const float4*)x)[i];
    __nv_bfloat16 h0 = __float2bfloat16(v.x);
    __nv_bfloat16 h1 = __float2bfloat16(v.y);
    __nv_bfloat16 h2 = __float2bfloat16(v.z);
    __nv_bfloat16 h3 = __float2bfloat16(v.w);
    float l0 = v.x - __bfloat162float(h0);
    float l1 = v.y - __bfloat162float(h1);
    float l2 = v.z - __bfloat162float(h2);
    float l3 = v.w - __bfloat162float(h3);
    __nv_bfloat162 hp0(h0, h1), hp1(h2, h3);
    *(uint2*)&g_xh[4 * i] = make_uint2(*(uint32_t*)&hp0, *(uint32_t*)&hp1);
    *(uint2*)&g_xl[4 * i] = make_uint2(pack_bf16(l0, l1), pack_bf16(l2, l3));
}

// ---------------------------------------------------------------------------
// prep_w: transpose + split W: g_wt[p][n][k] = split_bf16(W_p[k][n])
// ---------------------------------------------------------------------------
__global__ __launch_bounds__(256) void prep_w(const float* __restrict__ Wq,
                                              const float* __restrict__ Wk,
                                              const float* __restrict__ Wv)
{
    int i = blockIdx.x * 256 + threadIdx.x;   // 0 .. 3*131072-1
    int p   = i >> 17;
    int rem = i & 131071;
    int n = rem >> 10;
    int k = rem & 1023;
    const float* W = (p == 0) ? Wq : (p == 1) ? Wk : Wv;
    float v = W[k * H_SZ + n];
    __nv_bfloat16 h = __float2bfloat16(v);
    __nv_bfloat16 l = __float2bfloat16(v - __bfloat162float(h));
    g_wth[i] = h;
    g_wtl[i] = l;
}

// ---------------------------------------------------------------------------
// proj_tc: q/k/v = x @ W via mma.sync bf16-split. BM=128, BN=128, BK=64.
// Grid (3, 128): blockIdx.x = projection (adjacent bids share x slab -> L2).
// All tiles staged via cp.async (x pre-split by prep_x): A double-buffered
// (prefetch chunk c+1 during MMA of chunk c), B single-buffered (L2-hot W).
// Smem: A buf0 @0 (hi 16K, lo 16K), A buf1 @32768, B @65536 (hi, lo).
// Rows: 64 bf16 = 128B = 8 chunks of 16B, XOR-swizzled: chunk ^= row&7.
// ---------------------------------------------------------------------------
#define PROJ_SMEM 98304

__global__ __launch_bounds__(256, 2) void proj_tc()
{
    extern __shared__ __align__(128) char smem[];
    const uint32_t sb = smem_u32(smem);
    const uint32_t sB = sb + 65536;

    const int tid  = threadIdx.x;
    const int warp = tid >> 5;
    const int lane = tid & 31;
    const int warp_m = warp >> 1;
    const int warp_n = warp & 1;
    const int p    = blockIdx.x;
    const int row0 = blockIdx.y * 128;

    const __nv_bfloat16* wth = g_wth + (size_t)p * H_SZ * C_SZ;
    const __nv_bfloat16* wtl = g_wtl + (size_t)p * H_SZ * C_SZ;

    float D[2][8][4];
#pragma unroll
    for (int i = 0; i < 2; i++)
#pragma unroll
        for (int j = 0; j < 8; j++)
#pragma unroll
            for (int e = 0; e < 4; e++) D[i][j][e] = 0.0f;

    // --- staging lambdas (cp.async, one commit group each) ---
    auto issueA = [&](int c, int buf) {
        const int k0 = c * 64;
        const uint32_t base = sb + (uint32_t)buf * 32768;
#pragma unroll
        for (int it = 0; it < 4; it++) {
            int idx = it * 256 + tid;       // 0..1023
            int row = idx >> 3;
            int ch  = idx & 7;
            uint32_t soff = (uint32_t)(row * 128 + ((ch ^ (row & 7)) << 4));
            size_t g = (size_t)(row0 + row) * C_SZ + k0 + ch * 8;
            cp16(base + soff,         &g_xh[g]);
            cp16(base + 16384 + soff, &g_xl[g]);
        }
        CP_COMMIT();
    };
    auto issueB = [&](int c) {
        const int k0 = c * 64;
#pragma unroll
        for (int it = 0; it < 4; it++) {
            int idx = it * 256 + tid;
            int row = idx >> 3;
            int ch  = idx & 7;
            uint32_t soff = (uint32_t)(row * 128 + ((ch ^ (row & 7)) << 4));
            size_t g = (size_t)row * C_SZ + k0 + ch * 8;   // row == n
            cp16(sB + soff,         &wth[g]);
            cp16(sB + 16384 + soff, &wtl[g]);
        }
        CP_COMMIT();
    };

    issueA(0, 0);   // prefetch first A

    for (int c = 0; c < 16; c++) {
        if (c > 0) __syncthreads();      // MMA(c-1) readers done (A buf, B)
        issueB(c);
        issueA(c < 15 ? c + 1 : 15, (c + 1) & 1);   // clamped: uniform groups
        CP_WAIT1();                      // retires A(c) and B(c)
        __syncthreads();

        const uint32_t aB = sb + (uint32_t)(c & 1) * 32768;
#pragma unroll
        for (int ks = 0; ks < 4; ks++) {
            const int ch0 = ks * 2;
            uint32_t ah[2][4], al[2][4];
#pragma unroll
            for (int mf = 0; mf < 2; mf++) {
                int row = warp_m * 32 + mf * 16 + (lane & 15);
                int ch  = ch0 + (lane >> 4);
                uint32_t off = (uint32_t)(row * 128 + ((ch ^ (row & 7)) << 4));
                ldsm4(ah[mf], aB + off);
                ldsm4(al[mf], aB + 16384 + off);
            }
#pragma unroll
            for (int np = 0; np < 4; np++) {
                int nrow = warp_n * 64 + np * 16 + (lane & 7) + ((lane >> 4) << 3);
                int ch   = ch0 + ((lane >> 3) & 1);
                uint32_t off = (uint32_t)(nrow * 128 + ((ch ^ (nrow & 7)) << 4));
                uint32_t bh[4], bl[4];
                ldsm4(bh, sB + off);
                ldsm4(bl, sB + 16384 + off);
#pragma unroll
                for (int mf = 0; mf < 2; mf++) {
                    mma16816(D[mf][2 * np],     ah[mf], bh[0], bh[1]);
                    mma16816(D[mf][2 * np],     al[mf], bh[0], bh[1]);
                    mma16816(D[mf][2 * np],     ah[mf], bl[0], bl[1]);
                    mma16816(D[mf][2 * np + 1], ah[mf], bh[2], bh[3]);
                    mma16816(D[mf][2 * np + 1], al[mf], bh[2], bh[3]);
                    mma16816(D[mf][2 * np + 1], ah[mf], bl[2], bl[3]);
                }
            }
        }
    }
    CP_WAIT0();   // drain the clamped redundant prefetch

    // Epilogue: split-bf16 store to g_{q,k,v}{h,l}
    __nv_bfloat16* dh = (p == 0) ? g_qh : (p == 1) ? g_kh : g_vh;
    __nv_bfloat16* dl = (p == 0) ? g_ql : (p == 1) ? g_kl : g_vl;
    const float sc = (p == 0) ? SCALE : 1.0f;
    const int gid = lane >> 2;
    const int cb  = 2 * (lane & 3);
#pragma unroll
    for (int mf = 0; mf < 2; mf++) {
        int r0 = row0 + warp_m * 32 + mf * 16 + gid;
        int r1 = r0 + 8;
#pragma unroll
        for (int nf = 0; nf < 8; nf++) {
            int col = warp_n * 64 + nf * 8 + cb;
            float v0 = D[mf][nf][0] * sc, v1 = D[mf][nf][1] * sc;
            float v2 = D[mf][nf][2] * sc, v3 = D[mf][nf][3] * sc;
            uint32_t u0 = __float_as_uint(v0), u1 = __float_as_uint(v1);
            uint32_t u2 = __float_as_uint(v2), u3 = __float_as_uint(v3);
            uint32_t h01 = __byte_perm(u0, u1, 0x7632);
            uint32_t h23 = __byte_perm(u2, u3, 0x7632);
            float l0 = v0 - __uint_as_float(u0 & 0xffff0000u);
            float l1 = v1 - __uint_as_float(u1 & 0xffff0000u);
            float l2 = v2 - __uint_as_float(u2 & 0xffff0000u);
            float l3 = v3 - __uint_as_float(u3 & 0xffff0000u);
            *(uint32_t*)&dh[(size_t)r0 * H_SZ + col] = h01;
            *(uint32_t*)&dh[(size_t)r1 * H_SZ + col] = h23;
            *(uint32_t*)&dl[(size_t)r0 * H_SZ + col] = pack_bf16(l0, l1);
            *(uint32_t*)&dl[(size_t)r1 * H_SZ + col] = pack_bf16(l2, l3);
        }
    }
}

// ---------------------------------------------------------------------------
// attn_tc: flash attention via mma.sync bf16-split, cp.async pipelined.
// One 64-row q-tile per CTA, 128 threads (4 warps), CK=64, grid 256 with
// heavy-first pairing. Pipeline: K(c+1) prefetched during softmax/PV of
// chunk c; V(c) waited only after softmax (its load overlaps S compute).
// Uniform group accounting: every iter issues exactly one K and one V group
// (clamped at the last chunk), every wait is wait_group 1.
// ---------------------------------------------------------------------------
#define AT_SMEM 98304

__global__ __launch_bounds__(128, 2) void attn_tc(float* __restrict__ out)
{
    extern __shared__ __align__(128) char smem[];
    const uint32_t sb  = smem_u32(smem);
    const uint32_t sQh = sb;
    const uint32_t sQl = sb + 16384;
    const uint32_t sKh = sb + 32768;
    const uint32_t sKl = sb + 49152;
    const uint32_t sVh = sb + 65536;
    const uint32_t sVl = sb + 81920;

    const int tid  = threadIdx.x;
    const int warp = tid >> 5;
    const int lane = tid & 31;
    const int gid  = lane >> 2;
    const int cb   = 2 * (lane & 3);

    const int bid  = blockIdx.x;
    const int rank = (bid < 148) ? bid : 403 - bid;
    const int tile = 31 - (rank >> 3);
    const int b    = rank & 7;
    const int t0   = tile * 64;
    const int nchunks = tile + 1;

    const size_t bbase = (size_t)b * T_SZ * H_SZ;

    auto stage2 = [&](int r0, uint32_t dH, uint32_t dL,
                      const __nv_bfloat16* srcH, const __nv_bfloat16* srcL) {
#pragma unroll
        for (int it = 0; it < 8; it++) {
            int idx = it * 128 + tid;
            int row = idx >> 4;
            int ch  = idx & 15;
            uint32_t soff = (uint32_t)(row * 256 + ((ch ^ (row & 7)) << 4));
            size_t g = bbase + (size_t)(r0 + row) * H_SZ + ch * 8;
            cp16(dH + soff, &srcH[g]);
            cp16(dL + soff, &srcL[g]);
        }
    };

    // Preload: Q joins K(0)'s commit group; V(0) its own group.
    stage2(t0, sQh, sQl, g_qh, g_ql);
    stage2(0,  sKh, sKl, g_kh, g_kl);
    CP_COMMIT();
    stage2(0,  sVh, sVl, g_vh, g_vl);
    CP_COMMIT();

    float O[16][4];
#pragma unroll
    for (int i = 0; i < 16; i++)
#pragma unroll
        for (int e = 0; e < 4; e++) O[i][e] = 0.0f;
    float mr0 = -1e30f, mr1 = -1e30f, lr0 = 0.0f, lr1 = 0.0f;

    for (int c = 0; c < nchunks; c++) {
        const int cn = (c + 1 < nchunks) ? (c + 1) * 64 : (nchunks - 1) * 64;

        CP_WAIT1();          // K(c) (+Q on first iter) ready
        __syncthreads();

        // ---- S = Q K^T (split: QhKh + QlKh + QhKl) ----
        float S[8][4];
#pragma unroll
        for (int i = 0; i < 8; i++)
#pragma unroll
            for (int e = 0; e < 4; e++) S[i][e] = 0.0f;

#pragma unroll
        for (int kf = 0; kf < 8; kf++) {
            const int ch0 = kf * 2;
            uint32_t ah[4], al[4];
            {
                int row = warp * 16 + (lane & 15);
                int ch  = ch0 + (lane >> 4);
                uint32_t off = (uint32_t)(row * 256 + ((ch ^ (row & 7)) << 4));
                ldsm4(ah, sQh + off);
                ldsm4(al, sQl + off);
            }
#pragma unroll
            for (int np = 0; np < 4; np++) {
                int nrow = np * 16 + (lane & 7) + ((lane >> 4) << 3);
                int ch   = ch0 + ((lane >> 3) & 1);
                uint32_t off = (uint32_t)(nrow * 256 + ((ch ^ (nrow & 7)) << 4));
                uint32_t bh[4], bl[4];
                ldsm4(bh, sKh + off);
                ldsm4(bl, sKl + off);
                mma16816(S[2 * np],     ah, bh[0], bh[1]);
                mma16816(S[2 * np],     al, bh[0], bh[1]);
                mma16816(S[2 * np],     ah, bl[0], bl[1]);
                mma16816(S[2 * np + 1], ah, bh[2], bh[3]);
                mma16816(S[2 * np + 1], al, bh[2], bh[3]);
                mma16816(S[2 * np + 1], ah, bl[2], bl[3]);
            }
        }

        __syncthreads();                 // all warps done reading K
        stage2(cn, sKh, sKl, g_kh, g_kl);
        CP_COMMIT();                     // K(c+1) in flight under softmax+PV

        // ---- causal mask (only final chunk is diagonal) ----
        if (c == nchunks - 1) {
            int r0 = warp * 16 + gid;
#pragma unroll
            for (int nf = 0; nf < 8; nf++) {
                int j0 = nf * 8 + cb;
                if (j0     > r0)     S[nf][0] = -1e30f;
                if (j0 + 1 > r0)     S[nf][1] = -1e30f;
                if (j0     > r0 + 8) S[nf][2] = -1e30f;
                if (j0 + 1 > r0 + 8) S[nf][3] = -1e30f;
            }
        }

        // ---- online softmax ----
        float mx0 = mr0, mx1 = mr1;
#pragma unroll
        for (int nf = 0; nf < 8; nf++) {
            mx0 = fmaxf(mx0, fmaxf(S[nf][0], S[nf][1]));
            mx1 = fmaxf(mx1, fmaxf(S[nf][2], S[nf][3]));
        }
        mx0 = fmaxf(mx0, __shfl_xor_sync(0xffffffffu, mx0, 1));
        mx0 = fmaxf(mx0, __shfl_xor_sync(0xffffffffu, mx0, 2));
        mx1 = fmaxf(mx1, __shfl_xor_sync(0xffffffffu, mx1, 1));
        mx1 = fmaxf(mx1, __shfl_xor_sync(0xffffffffu, mx1, 2));
        float corr0 = __expf(mr0 - mx0);
        float corr1 = __expf(mr1 - mx1);
        float sum0 = 0.0f, sum1 = 0.0f;
#pragma unroll
        for (int nf = 0; nf < 8; nf++) {
            S[nf][0] = __expf(S[nf][0] - mx0); sum0 += S[nf][0];
            S[nf][1] = __expf(S[nf][1] - mx0); sum0 += S[nf][1];
            S[nf][2] = __expf(S[nf][2] - mx1); sum1 += S[nf][2];
            S[nf][3] = __expf(S[nf][3] - mx1); sum1 += S[nf][3];
        }
        sum0 += __shfl_xor_sync(0xffffffffu, sum0, 1);
        sum0 += __shfl_xor_sync(0xffffffffu, sum0, 2);
        sum1 += __shfl_xor_sync(0xffffffffu, sum1, 1);
        sum1 += __shfl_xor_sync(0xffffffffu, sum1, 2);
        lr0 = lr0 * corr0 + sum0;  mr0 = mx0;
        lr1 = lr1 * corr1 + sum1;  mr1 = mx1;
#pragma unroll
        for (int nf = 0; nf < 16; nf++) {
            O[nf][0] *= corr0; O[nf][1] *= corr0;
            O[nf][2] *= corr1; O[nf][3] *= corr1;
        }

        CP_WAIT1();          // V(c) ready (loaded under S compute)
        __syncthreads();

        // ---- O += P V (split: PhVh + PlVh + PhVl) ----
#pragma unroll
        for (int kf = 0; kf < 4; kf++) {
            uint32_t ph[4], pl[4];
            {
                float s00 = S[2*kf][0],   s01 = S[2*kf][1];
                float s02 = S[2*kf][2],   s03 = S[2*kf][3];
                float s10 = S[2*kf+1][0], s11 = S[2*kf+1][1];
                float s12 = S[2*kf+1][2], s13 = S[2*kf+1][3];
                uint32_t u00 = __float_as_uint(s00), u01 = __float_as_uint(s01);
                uint32_t u02 = __float_as_uint(s02), u03 = __float_as_uint(s03);
                uint32_t u10 = __float_as_uint(s10), u11 = __float_as_uint(s11);
                uint32_t u12 = __float_as_uint(s12), u13 = __float_as_uint(s13);
                ph[0] = __byte_perm(u00, u01, 0x7632);
                ph[1] = __byte_perm(u02, u03, 0x7632);
                ph[2] = __byte_perm(u10, u11, 0x7632);
                ph[3] = __byte_perm(u12, u13, 0x7632);
                pl[0] = pack_bf16(s00 - __uint_as_float(u00 & 0xffff0000u),
                                  s01 - __uint_as_float(u01 & 0xffff0000u));
                pl[1] = pack_bf16(s02 - __uint_as_float(u02 & 0xffff0000u),
                                  s03 - __uint_as_float(u03 & 0xffff0000u));
                pl[2] = pack_bf16(s10 - __uint_as_float(u10 & 0xffff0000u),
                                  s11 - __uint_as_float(u11 & 0xffff0000u));
                pl[3] = pack_bf16(s12 - __uint_as_float(u12 & 0xffff0000u),
                                  s13 - __uint_as_float(u13 & 0xffff0000u));
            }
#pragma unroll
            for (int np = 0; np < 8; np++) {
                int row = kf * 16 + (lane & 7) + (((lane >> 3) & 1) << 3);
                int ch  = np * 2 + (lane >> 4);
                uint32_t off = (uint32_t)(row * 256 + ((ch ^ (row & 7)) << 4));
                uint32_t vh[4], vl[4];
                ldsm4t(vh, sVh + off);
                ldsm4t(vl, sVl + off);
                mma16816(O[2 * np],     ph, vh[0], vh[1]);
                mma16816(O[2 * np],     pl, vh[0], vh[1]);
                mma16816(O[2 * np],     ph, vl[0], vl[1]);
                mma16816(O[2 * np + 1], ph, vh[2], vh[3]);
                mma16816(O[2 * np + 1], pl, vh[2], vh[3]);
                mma16816(O[2 * np + 1], ph, vl[2], vl[3]);
            }
        }

        __syncthreads();                 // all warps done reading V
        stage2(cn, sVh, sVl, g_vh, g_vl);
        CP_COMMIT();                     // V(c+1) in flight under next S
    }
    CP_WAIT0();   // drain clamped redundant prefetch before exit

    // ---- finalize + store ----
    float inv0 = 1.0f / lr0;
    float inv1 = 1.0f / lr1;
    size_t rg0 = (size_t)b * T_SZ + t0 + warp * 16 + gid;
    size_t rg1 = rg0 + 8;
#pragma unroll
    for (int nf = 0; nf < 16; nf++) {
        int col = nf * 8 + cb;
        float2 v0 = make_float2(O[nf][0] * inv0, O[nf][1] * inv0);
        float2 v1 = make_float2(O[nf][2] * inv1, O[nf][3] * inv1);
        *(float2*)&out[rg0 * H_SZ + col] = v0;
        *(float2*)&out[rg1 * H_SZ + col] = v1;
    }
}

// ---------------------------------------------------------------------------
extern "C" void kernel_launch(void* const* d_in, const int* in_sizes, int n_in,
                              void* d_out, int out_size)
{
    const float* x  = (const float*)d_in[0];   // [8,2048,1024]
    const float* Wq = (const float*)d_in[1];   // [1024,128]
    const float* Wk = (const float*)d_in[2];
    const float* Wv = (const float*)d_in[3];
    float* out = (float*)d_out;                // [8,2048,128]

    cudaFuncSetAttribute(proj_tc, cudaFuncAttributeMaxDynamicSharedMemorySize,
                         PROJ_SMEM);
    cudaFuncSetAttribute(attn_tc, cudaFuncAttributeMaxDynamicSharedMemorySize,
                         AT_SMEM);

    prep_x<<<(ROWS * C_SZ / 4) / 256, 256>>>(x);
    prep_w<<<(3 * H_SZ * C_SZ) / 256, 256>>>(Wq, Wk, Wv);
    proj_tc<<<dim3(3, ROWS / 128), 256, PROJ_SMEM>>>();
    attn_tc<<<256, 128, AT_SMEM>>>(out);
}

// round 13
// speedup vs baseline: 5.4662x; 1.1138x over previous
#include <cuda_runtime.h>
#include <cuda_bf16.h>
#include <cuda_fp16.h>
#include <cstdint>

// Problem constants
#define B_SZ   8
#define T_SZ   2048
#define C_SZ   1024
#define H_SZ   128
#define ROWS   (B_SZ * T_SZ)       // 16384
#define SCALE  (0.03125f)          // C^-0.5 = 1/32

// Scratch (device statics: allocation-free rule)
__device__ __nv_bfloat16 g_xh[ROWS * C_SZ];        // split-bf16 of x (proj)
__device__ __nv_bfloat16 g_xl[ROWS * C_SZ];
__device__ __nv_bfloat16 g_wth[3 * H_SZ * C_SZ];   // W^T split: [proj][n][k]
__device__ __nv_bfloat16 g_wtl[3 * H_SZ * C_SZ];
__device__ __half g_qh[ROWS * H_SZ];               // q/32, fp16 split
__device__ __half g_ql[ROWS * H_SZ];
__device__ __half g_kx[ROWS * H_SZ];               // k, fp16 single
__device__ __half g_vx[ROWS * H_SZ];               // v, fp16 single

// ---------------------------------------------------------------------------
// Helpers
// ---------------------------------------------------------------------------
__device__ __forceinline__ uint32_t smem_u32(const void* p) {
    uint32_t a;
    asm("{ .reg .u64 t; cvta.to.shared.u64 t, %1; cvt.u32.u64 %0, t; }"
        : "=r"(a) : "l"(p));
    return a;
}
__device__ __forceinline__ void ldsm4(uint32_t* r, uint32_t addr) {
    asm volatile("ldmatrix.sync.aligned.m8n8.x4.shared.b16 {%0,%1,%2,%3}, [%4];"
                 : "=r"(r[0]), "=r"(r[1]), "=r"(r[2]), "=r"(r[3]) : "r"(addr));
}
__device__ __forceinline__ void ldsm4t(uint32_t* r, uint32_t addr) {
    asm volatile("ldmatrix.sync.aligned.m8n8.x4.trans.shared.b16 {%0,%1,%2,%3}, [%4];"
                 : "=r"(r[0]), "=r"(r[1]), "=r"(r[2]), "=r"(r[3]) : "r"(addr));
}
__device__ __forceinline__ void mma16816bf(float* d, const uint32_t* a,
                                           uint32_t b0, uint32_t b1) {
    asm volatile(
        "mma.sync.aligned.m16n8k16.row.col.f32.bf16.bf16.f32 "
        "{%0,%1,%2,%3}, {%4,%5,%6,%7}, {%8,%9}, {%0,%1,%2,%3};"
        : "+f"(d[0]), "+f"(d[1]), "+f"(d[2]), "+f"(d[3])
        : "r"(a[0]), "r"(a[1]), "r"(a[2]), "r"(a[3]), "r"(b0), "r"(b1));
}
__device__ __forceinline__ void mma16816h(float* d, const uint32_t* a,
                                          uint32_t b0, uint32_t b1) {
    asm volatile(
        "mma.sync.aligned.m16n8k16.row.col.f32.f16.f16.f32 "
        "{%0,%1,%2,%3}, {%4,%5,%6,%7}, {%8,%9}, {%0,%1,%2,%3};"
        : "+f"(d[0]), "+f"(d[1]), "+f"(d[2]), "+f"(d[3])
        : "r"(a[0]), "r"(a[1]), "r"(a[2]), "r"(a[3]), "r"(b0), "r"(b1));
}
// pack two fp32 -> bf16x2 (lo lane = first arg)
__device__ __forceinline__ uint32_t pack_bf16(float lo, float hi) {
    uint32_t r;
    asm("cvt.rn.bf16x2.f32 %0, %1, %2;" : "=r"(r) : "f"(hi), "f"(lo));
    return r;
}
// split (a,b) fp32 -> fp16 hi pair + fp16 residual pair
__device__ __forceinline__ void split_h2(float a, float b,
                                         uint32_t& h, uint32_t& l) {
    __half2 hh = __floats2half2_rn(a, b);
    float2 hf = __half22float2(hh);
    __half2 ll = __floats2half2_rn(a - hf.x, b - hf.y);
    h = *reinterpret_cast<uint32_t*>(&hh);
    l = *reinterpret_cast<uint32_t*>(&ll);
}
__device__ __forceinline__ void cp16(uint32_t dst, const void* src) {
    asm volatile("cp.async.cg.shared.global [%0], [%1], 16;"
                 :: "r"(dst), "l"(src));
}
#define CP_COMMIT() asm volatile("cp.async.commit_group;" ::: "memory")
#define CP_WAIT0()  asm volatile("cp.async.wait_group 0;" ::: "memory")
#define CP_WAIT1()  asm volatile("cp.async.wait_group 1;" ::: "memory")

// ---------------------------------------------------------------------------
// prep_x: split x (fp32) into bf16 hi/lo pair (memory-bound, once)
// ---------------------------------------------------------------------------
__global__ __launch_bounds__(256) void prep_x(const float* __restrict__ x)
{
    size_t i = (size_t)blockIdx.x * 256 + threadIdx.x;   // float4 index
    float4 v = ((const float4*)x)[i];
    __nv_bfloat16 h0 = __float2bfloat16(v.x);
    __nv_bfloat16 h1 = __float2bfloat16(v.y);
    __nv_bfloat16 h2 = __float2bfloat16(v.z);
    __nv_bfloat16 h3 = __float2bfloat16(v.w);
    float l0 = v.x - __bfloat162float(h0);
    float l1 = v.y - __bfloat162float(h1);
    float l2 = v.z - __bfloat162float(h2);
    float l3 = v.w - __bfloat162float(h3);
    __nv_bfloat162 hp0(h0, h1), hp1(h2, h3);
    *(uint2*)&g_xh[4 * i] = make_uint2(*(uint32_t*)&hp0, *(uint32_t*)&hp1);
    *(uint2*)&g_xl[4 * i] = make_uint2(pack_bf16(l0, l1), pack_bf16(l2, l3));
}

// ---------------------------------------------------------------------------
// prep_w: transpose + split W: g_wt[p][n][k] = split_bf16(W_p[k][n])
// ---------------------------------------------------------------------------
__global__ __launch_bounds__(256) void prep_w(const float* __restrict__ Wq,
                                              const float* __restrict__ Wk,
                                              const float* __restrict__ Wv)
{
    int i = blockIdx.x * 256 + threadIdx.x;   // 0 .. 3*131072-1
    int p   = i >> 17;
    int rem = i & 131071;
    int n = rem >> 10;
    int k = rem & 1023;
    const float* W = (p == 0) ? Wq : (p == 1) ? Wk : Wv;
    float v = W[k * H_SZ + n];
    __nv_bfloat16 h = __float2bfloat16(v);
    __nv_bfloat16 l = __float2bfloat16(v - __bfloat162float(h));
    g_wth[i] = h;
    g_wtl[i] = l;
}

// ---------------------------------------------------------------------------
// proj_tc: q/k/v = x @ W via mma.sync bf16-split (3 products, err ~1.7e-5).
// BM=128, BN=128, BK=64. Grid (3, 128), 256 threads, A double-buffered via
// cp.async, B single-buffered (L2-hot). Epilogue: q -> fp16 split (scaled),
// k/v -> fp16 single.
// ---------------------------------------------------------------------------
#define PROJ_SMEM 98304

__global__ __launch_bounds__(256, 2) void proj_tc()
{
    extern __shared__ __align__(128) char smem[];
    const uint32_t sb = smem_u32(smem);
    const uint32_t sB = sb + 65536;

    const int tid  = threadIdx.x;
    const int warp = tid >> 5;
    const int lane = tid & 31;
    const int warp_m = warp >> 1;
    const int warp_n = warp & 1;
    const int p    = blockIdx.x;
    const int row0 = blockIdx.y * 128;

    const __nv_bfloat16* wth = g_wth + (size_t)p * H_SZ * C_SZ;
    const __nv_bfloat16* wtl = g_wtl + (size_t)p * H_SZ * C_SZ;

    float D[2][8][4];
#pragma unroll
    for (int i = 0; i < 2; i++)
#pragma unroll
        for (int j = 0; j < 8; j++)
#pragma unroll
            for (int e = 0; e < 4; e++) D[i][j][e] = 0.0f;

    auto issueA = [&](int c, int buf) {
        const int k0 = c * 64;
        const uint32_t base = sb + (uint32_t)buf * 32768;
#pragma unroll
        for (int it = 0; it < 4; it++) {
            int idx = it * 256 + tid;       // 0..1023
            int row = idx >> 3;
            int ch  = idx & 7;
            uint32_t soff = (uint32_t)(row * 128 + ((ch ^ (row & 7)) << 4));
            size_t g = (size_t)(row0 + row) * C_SZ + k0 + ch * 8;
            cp16(base + soff,         &g_xh[g]);
            cp16(base + 16384 + soff, &g_xl[g]);
        }
        CP_COMMIT();
    };
    auto issueB = [&](int c) {
        const int k0 = c * 64;
#pragma unroll
        for (int it = 0; it < 4; it++) {
            int idx = it * 256 + tid;
            int row = idx >> 3;
            int ch  = idx & 7;
            uint32_t soff = (uint32_t)(row * 128 + ((ch ^ (row & 7)) << 4));
            size_t g = (size_t)row * C_SZ + k0 + ch * 8;   // row == n
            cp16(sB + soff,         &wth[g]);
            cp16(sB + 16384 + soff, &wtl[g]);
        }
        CP_COMMIT();
    };

    issueA(0, 0);

    for (int c = 0; c < 16; c++) {
        if (c > 0) __syncthreads();
        issueB(c);
        issueA(c < 15 ? c + 1 : 15, (c + 1) & 1);
        CP_WAIT1();
        __syncthreads();

        const uint32_t aB = sb + (uint32_t)(c & 1) * 32768;
#pragma unroll
        for (int ks = 0; ks < 4; ks++) {
            const int ch0 = ks * 2;
            uint32_t ah[2][4], al[2][4];
#pragma unroll
            for (int mf = 0; mf < 2; mf++) {
                int row = warp_m * 32 + mf * 16 + (lane & 15);
                int ch  = ch0 + (lane >> 4);
                uint32_t off = (uint32_t)(row * 128 + ((ch ^ (row & 7)) << 4));
                ldsm4(ah[mf], aB + off);
                ldsm4(al[mf], aB + 16384 + off);
            }
#pragma unroll
            for (int np = 0; np < 4; np++) {
                int nrow = warp_n * 64 + np * 16 + (lane & 7) + ((lane >> 4) << 3);
                int ch   = ch0 + ((lane >> 3) & 1);
                uint32_t off = (uint32_t)(nrow * 128 + ((ch ^ (nrow & 7)) << 4));
                uint32_t bh[4], bl[4];
                ldsm4(bh, sB + off);
                ldsm4(bl, sB + 16384 + off);
#pragma unroll
                for (int mf = 0; mf < 2; mf++) {
                    mma16816bf(D[mf][2 * np],     ah[mf], bh[0], bh[1]);
                    mma16816bf(D[mf][2 * np],     al[mf], bh[0], bh[1]);
                    mma16816bf(D[mf][2 * np],     ah[mf], bl[0], bl[1]);
                    mma16816bf(D[mf][2 * np + 1], ah[mf], bh[2], bh[3]);
                    mma16816bf(D[mf][2 * np + 1], al[mf], bh[2], bh[3]);
                    mma16816bf(D[mf][2 * np + 1], ah[mf], bl[2], bl[3]);
                }
            }
        }
    }
    CP_WAIT0();

    // Epilogue: q -> fp16 split (scaled by 1/32); k/v -> fp16 single
    const int gid = lane >> 2;
    const int cb  = 2 * (lane & 3);
    if (p == 0) {
#pragma unroll
        for (int mf = 0; mf < 2; mf++) {
            int r0 = row0 + warp_m * 32 + mf * 16 + gid;
            int r1 = r0 + 8;
#pragma unroll
            for (int nf = 0; nf < 8; nf++) {
                int col = warp_n * 64 + nf * 8 + cb;
                float v0 = D[mf][nf][0] * SCALE, v1 = D[mf][nf][1] * SCALE;
                float v2 = D[mf][nf][2] * SCALE, v3 = D[mf][nf][3] * SCALE;
                uint32_t h01, l01, h23, l23;
                split_h2(v0, v1, h01, l01);
                split_h2(v2, v3, h23, l23);
                *(uint32_t*)&g_qh[(size_t)r0 * H_SZ + col] = h01;
                *(uint32_t*)&g_ql[(size_t)r0 * H_SZ + col] = l01;
                *(uint32_t*)&g_qh[(size_t)r1 * H_SZ + col] = h23;
                *(uint32_t*)&g_ql[(size_t)r1 * H_SZ + col] = l23;
            }
        }
    } else {
        __half* dst = (p == 1) ? g_kx : g_vx;
#pragma unroll
        for (int mf = 0; mf < 2; mf++) {
            int r0 = row0 + warp_m * 32 + mf * 16 + gid;
            int r1 = r0 + 8;
#pragma unroll
            for (int nf = 0; nf < 8; nf++) {
                int col = warp_n * 64 + nf * 8 + cb;
                __half2 a = __floats2half2_rn(D[mf][nf][0], D[mf][nf][1]);
                __half2 b = __floats2half2_rn(D[mf][nf][2], D[mf][nf][3]);
                *(uint32_t*)&dst[(size_t)r0 * H_SZ + col] = *(uint32_t*)&a;
                *(uint32_t*)&dst[(size_t)r1 * H_SZ + col] = *(uint32_t*)&b;
            }
        }
    }
}

// ---------------------------------------------------------------------------
// attn_tc: flash attention, fp16 asymmetric split:
//   S = Qh·K + Ql·K   (Q split fp16, K single fp16)  -> 2 MMAs/frag
//   O = Ph·V + Pl·V   (P split fp16, V single fp16)  -> 2 MMAs/frag
// One 64-row q-tile per CTA, 4 warps, CK=64, grid 256 heavy-first pairing.
// K and V truly double-buffered via cp.async, full-chunk prefetch distance.
// Smem: Qh 16K | Ql 16K | K x2 16K | V x2 16K = 96KB. Rows 256B, 16 chunks,
// XOR swizzle chunk ^= row&7.
// ---------------------------------------------------------------------------
#define AT_SMEM 98304

__global__ __launch_bounds__(128, 2) void attn_tc(float* __restrict__ out)
{
    extern __shared__ __align__(128) char smem[];
    const uint32_t sb  = smem_u32(smem);
    const uint32_t sQh = sb;
    const uint32_t sQl = sb + 16384;
    const uint32_t sK  = sb + 32768;   // + 16384*buf
    const uint32_t sV  = sb + 65536;   // + 16384*buf

    const int tid  = threadIdx.x;
    const int warp = tid >> 5;
    const int lane = tid & 31;
    const int gid  = lane >> 2;
    const int cb   = 2 * (lane & 3);

    const int bid  = blockIdx.x;
    const int rank = (bid < 148) ? bid : 403 - bid;
    const int tile = 31 - (rank >> 3);
    const int b    = rank & 7;
    const int t0   = tile * 64;
    const int nchunks = tile + 1;

    const size_t bbase = (size_t)b * T_SZ * H_SZ;

    auto stage1 = [&](int r0, uint32_t dst, const __half* src) {
#pragma unroll
        for (int it = 0; it < 8; it++) {
            int idx = it * 128 + tid;
            int row = idx >> 4;
            int ch  = idx & 15;
            uint32_t soff = (uint32_t)(row * 256 + ((ch ^ (row & 7)) << 4));
            cp16(dst + soff, &src[bbase + (size_t)(r0 + row) * H_SZ + ch * 8]);
        }
    };

    // Preload Q + K(0) + V(0), one group
    stage1(t0, sQh, g_qh);
    stage1(t0, sQl, g_ql);
    stage1(0,  sK,  g_kx);
    stage1(0,  sV,  g_vx);
    CP_COMMIT();

    float O[16][4];
#pragma unroll
    for (int i = 0; i < 16; i++)
#pragma unroll
        for (int e = 0; e < 4; e++) O[i][e] = 0.0f;
    float mr0 = -1e30f, mr1 = -1e30f, lr0 = 0.0f, lr1 = 0.0f;

    for (int c = 0; c < nchunks; c++) {
        CP_WAIT0();          // chunk c data ready
        __syncthreads();     // + everyone done with buffer (c+1)&1 (chunk c-1)

        if (c + 1 < nchunks) {   // prefetch next chunk under full compute
            int nb = (c + 1) & 1;
            stage1((c + 1) * 64, sK + nb * 16384, g_kx);
            stage1((c + 1) * 64, sV + nb * 16384, g_vx);
        }
        CP_COMMIT();

        const uint32_t kB = sK + (uint32_t)(c & 1) * 16384;
        const uint32_t vB = sV + (uint32_t)(c & 1) * 16384;

        // ---- S = Qh·K + Ql·K ----
        float S[8][4];
#pragma unroll
        for (int i = 0; i < 8; i++)
#pragma unroll
            for (int e = 0; e < 4; e++) S[i][e] = 0.0f;

#pragma unroll
        for (int kf = 0; kf < 8; kf++) {
            const int ch0 = kf * 2;
            uint32_t ah[4], al[4];
            {
                int row = warp * 16 + (lane & 15);
                int ch  = ch0 + (lane >> 4);
                uint32_t off = (uint32_t)(row * 256 + ((ch ^ (row & 7)) << 4));
                ldsm4(ah, sQh + off);
                ldsm4(al, sQl + off);
            }
#pragma unroll
            for (int np = 0; np < 4; np++) {
                int nrow = np * 16 + (lane & 7) + ((lane >> 4) << 3);
                int ch   = ch0 + ((lane >> 3) & 1);
                uint32_t off = (uint32_t)(nrow * 256 + ((ch ^ (nrow & 7)) << 4));
                uint32_t bk[4];
                ldsm4(bk, kB + off);
                mma16816h(S[2 * np],     ah, bk[0], bk[1]);
                mma16816h(S[2 * np],     al, bk[0], bk[1]);
                mma16816h(S[2 * np + 1], ah, bk[2], bk[3]);
                mma16816h(S[2 * np + 1], al, bk[2], bk[3]);
            }
        }

        // ---- causal mask (only final chunk is diagonal) ----
        if (c == nchunks - 1) {
            int r0 = warp * 16 + gid;
#pragma unroll
            for (int nf = 0; nf < 8; nf++) {
                int j0 = nf * 8 + cb;
                if (j0     > r0)     S[nf][0] = -1e30f;
                if (j0 + 1 > r0)     S[nf][1] = -1e30f;
                if (j0     > r0 + 8) S[nf][2] = -1e30f;
                if (j0 + 1 > r0 + 8) S[nf][3] = -1e30f;
            }
        }

        // ---- online softmax ----
        float mx0 = mr0, mx1 = mr1;
#pragma unroll
        for (int nf = 0; nf < 8; nf++) {
            mx0 = fmaxf(mx0, fmaxf(S[nf][0], S[nf][1]));
            mx1 = fmaxf(mx1, fmaxf(S[nf][2], S[nf][3]));
        }
        mx0 = fmaxf(mx0, __shfl_xor_sync(0xffffffffu, mx0, 1));
        mx0 = fmaxf(mx0, __shfl_xor_sync(0xffffffffu, mx0, 2));
        mx1 = fmaxf(mx1, __shfl_xor_sync(0xffffffffu, mx1, 1));
        mx1 = fmaxf(mx1, __shfl_xor_sync(0xffffffffu, mx1, 2));
        float corr0 = __expf(mr0 - mx0);
        float corr1 = __expf(mr1 - mx1);
        float sum0 = 0.0f, sum1 = 0.0f;
#pragma unroll
        for (int nf = 0; nf < 8; nf++) {
            S[nf][0] = __expf(S[nf][0] - mx0); sum0 += S[nf][0];
            S[nf][1] = __expf(S[nf][1] - mx0); sum0 += S[nf][1];
            S[nf][2] = __expf(S[nf][2] - mx1); sum1 += S[nf][2];
            S[nf][3] = __expf(S[nf][3] - mx1); sum1 += S[nf][3];
        }
        sum0 += __shfl_xor_sync(0xffffffffu, sum0, 1);
        sum0 += __shfl_xor_sync(0xffffffffu, sum0, 2);
        sum1 += __shfl_xor_sync(0xffffffffu, sum1, 1);
        sum1 += __shfl_xor_sync(0xffffffffu, sum1, 2);
        lr0 = lr0 * corr0 + sum0;  mr0 = mx0;
        lr1 = lr1 * corr1 + sum1;  mr1 = mx1;
#pragma unroll
        for (int nf = 0; nf < 16; nf++) {
            O[nf][0] *= corr0; O[nf][1] *= corr0;
            O[nf][2] *= corr1; O[nf][3] *= corr1;
        }

        // ---- O += Ph·V + Pl·V ----
#pragma unroll
        for (int kf = 0; kf < 4; kf++) {
            uint32_t ph[4], pl[4];
            split_h2(S[2*kf][0],   S[2*kf][1],   ph[0], pl[0]);
            split_h2(S[2*kf][2],   S[2*kf][3],   ph[1], pl[1]);
            split_h2(S[2*kf+1][0], S[2*kf+1][1], ph[2], pl[2]);
            split_h2(S[2*kf+1][2], S[2*kf+1][3], ph[3], pl[3]);
#pragma unroll
            for (int np = 0; np < 8; np++) {
                int row = kf * 16 + (lane & 7) + (((lane >> 3) & 1) << 3);
                int ch  = np * 2 + (lane >> 4);
                uint32_t off = (uint32_t)(row * 256 + ((ch ^ (row & 7)) << 4));
                uint32_t vv[4];
                ldsm4t(vv, vB + off);
                mma16816h(O[2 * np],     ph, vv[0], vv[1]);
                mma16816h(O[2 * np],     pl, vv[0], vv[1]);
                mma16816h(O[2 * np + 1], ph, vv[2], vv[3]);
                mma16816h(O[2 * np + 1], pl, vv[2], vv[3]);
            }
        }
    }
    CP_WAIT0();

    // ---- finalize + store ----
    float inv0 = 1.0f / lr0;
    float inv1 = 1.0f / lr1;
    size_t rg0 = (size_t)b * T_SZ + t0 + warp * 16 + gid;
    size_t rg1 = rg0 + 8;
#pragma unroll
    for (int nf = 0; nf < 16; nf++) {
        int col = nf * 8 + cb;
        float2 v0 = make_float2(O[nf][0] * inv0, O[nf][1] * inv0);
        float2 v1 = make_float2(O[nf][2] * inv1, O[nf][3] * inv1);
        *(float2*)&out[rg0 * H_SZ + col] = v0;
        *(float2*)&out[rg1 * H_SZ + col] = v1;
    }
}

// ---------------------------------------------------------------------------
extern "C" void kernel_launch(void* const* d_in, const int* in_sizes, int n_in,
                              void* d_out, int out_size)
{
    const float* x  = (const float*)d_in[0];   // [8,2048,1024]
    const float* Wq = (const float*)d_in[1];   // [1024,128]
    const float* Wk = (const float*)d_in[2];
    const float* Wv = (const float*)d_in[3];
    float* out = (float*)d_out;                // [8,2048,128]

    cudaFuncSetAttribute(proj_tc, cudaFuncAttributeMaxDynamicSharedMemorySize,
                         PROJ_SMEM);
    cudaFuncSetAttribute(attn_tc, cudaFuncAttributeMaxDynamicSharedMemorySize,
                         AT_SMEM);

    prep_x<<<(ROWS * C_SZ / 4) / 256, 256>>>(x);
    prep_w<<<(3 * H_SZ * C_SZ) / 256, 256>>>(Wq, Wk, Wv);
    proj_tc<<<dim3(3, ROWS / 128), 256, PROJ_SMEM>>>();
    attn_tc<<<256, 128, AT_SMEM>>>(out);
}

// round 16
// speedup vs baseline: 6.4850x; 1.1864x over previous
#include <cuda_runtime.h>
#include <cuda_bf16.h>
#include <cuda_fp16.h>
#include <cstdint>

// Problem constants
#define B_SZ   8
#define T_SZ   2048
#define C_SZ   1024
#define H_SZ   128
#define ROWS   (B_SZ * T_SZ)       // 16384
#define SCALE  (0.03125f)          // C^-0.5 = 1/32

// Scratch (device statics: allocation-free rule)
__device__ __half g_xh[ROWS * C_SZ];     // x split fp16 (hi)
__device__ __half g_xl[ROWS * C_SZ];     // x split fp16 (lo residual)
__device__ __half g_wt[3 * H_SZ * C_SZ]; // W^T single fp16: [proj][n][k]
__device__ __half g_qh[ROWS * H_SZ];     // q/32, fp16 split
__device__ __half g_ql[ROWS * H_SZ];
__device__ __half g_kx[ROWS * H_SZ];     // k, fp16 single
__device__ __half g_vx[ROWS * H_SZ];     // v, fp16 single

// ---------------------------------------------------------------------------
// Helpers
// ---------------------------------------------------------------------------
__device__ __forceinline__ uint32_t smem_u32(const void* p) {
    uint32_t a;
    asm("{ .reg .u64 t; cvta.to.shared.u64 t, %1; cvt.u32.u64 %0, t; }"
        : "=r"(a) : "l"(p));
    return a;
}
__device__ __forceinline__ void ldsm4(uint32_t* r, uint32_t addr) {
    asm volatile("ldmatrix.sync.aligned.m8n8.x4.shared.b16 {%0,%1,%2,%3}, [%4];"
                 : "=r"(r[0]), "=r"(r[1]), "=r"(r[2]), "=r"(r[3]) : "r"(addr));
}
__device__ __forceinline__ void ldsm4t(uint32_t* r, uint32_t addr) {
    asm volatile("ldmatrix.sync.aligned.m8n8.x4.trans.shared.b16 {%0,%1,%2,%3}, [%4];"
                 : "=r"(r[0]), "=r"(r[1]), "=r"(r[2]), "=r"(r[3]) : "r"(addr));
}
__device__ __forceinline__ void mma16816h(float* d, const uint32_t* a,
                                          uint32_t b0, uint32_t b1) {
    asm volatile(
        "mma.sync.aligned.m16n8k16.row.col.f32.f16.f16.f32 "
        "{%0,%1,%2,%3}, {%4,%5,%6,%7}, {%8,%9}, {%0,%1,%2,%3};"
        : "+f"(d[0]), "+f"(d[1]), "+f"(d[2]), "+f"(d[3])
        : "r"(a[0]), "r"(a[1]), "r"(a[2]), "r"(a[3]), "r"(b0), "r"(b1));
}
// split (a,b) fp32 -> fp16 hi pair + fp16 residual pair
__device__ __forceinline__ void split_h2(float a, float b,
                                         uint32_t& h, uint32_t& l) {
    __half2 hh = __floats2half2_rn(a, b);
    float2 hf = __half22float2(hh);
    __half2 ll = __floats2half2_rn(a - hf.x, b - hf.y);
    h = *reinterpret_cast<uint32_t*>(&hh);
    l = *reinterpret_cast<uint32_t*>(&ll);
}
__device__ __forceinline__ void cp16(uint32_t dst, const void* src) {
    asm volatile("cp.async.cg.shared.global [%0], [%1], 16;"
                 :: "r"(dst), "l"(src));
}
#define CP_COMMIT() asm volatile("cp.async.commit_group;" ::: "memory")
#define CP_WAIT0()  asm volatile("cp.async.wait_group 0;" ::: "memory")
#define CP_WAIT1()  asm volatile("cp.async.wait_group 1;" ::: "memory")

// ---------------------------------------------------------------------------
// prep_x: split x (fp32) into fp16 hi/lo pair (memory-bound, once)
// ---------------------------------------------------------------------------
__global__ __launch_bounds__(256) void prep_x(const float* __restrict__ x)
{
    size_t i = (size_t)blockIdx.x * 256 + threadIdx.x;   // float4 index
    float4 v = ((const float4*)x)[i];
    uint32_t h01, l01, h23, l23;
    split_h2(v.x, v.y, h01, l01);
    split_h2(v.z, v.w, h23, l23);
    *(uint2*)&g_xh[4 * i] = make_uint2(h01, h23);
    *(uint2*)&g_xl[4 * i] = make_uint2(l01, l23);
}

// ---------------------------------------------------------------------------
// prep_w: transpose W to fp16 single: g_wt[p][n][k] = fp16(W_p[k][n])
// ---------------------------------------------------------------------------
__global__ __launch_bounds__(256) void prep_w(const float* __restrict__ Wq,
                                              const float* __restrict__ Wk,
                                              const float* __restrict__ Wv)
{
    int i = blockIdx.x * 256 + threadIdx.x;   // 0 .. 3*131072-1
    int p   = i >> 17;
    int rem = i & 131071;
    int n = rem >> 10;
    int k = rem & 1023;
    const float* W = (p == 0) ? Wq : (p == 1) ? Wk : Wv;
    g_wt[i] = __float2half(W[k * H_SZ + n]);
}

// ---------------------------------------------------------------------------
// proj_tc: q/k/v = x @ W via mma.sync, fp16 asymmetric split:
//   D = xh·W + xl·W  (x split fp16, W single fp16) -> 2 MMAs/frag.
// BM=128, BN=128, BK=64. Grid (3, 128), 256 threads. A (hi+lo) and B both
// double-buffered via cp.async, one commit group per chunk, wait_group 1.
// Smem: Abuf0 {Ah@0, Al@16K} | Abuf1 @32K | Bbuf0 @64K | Bbuf1 @80K = 96KB.
// Rows: 64 fp16 = 128B = 8 chunks of 16B, XOR-swizzled: chunk ^= row&7.
// Epilogue: q -> fp16 split (scaled by 1/32), k/v -> fp16 single.
// ---------------------------------------------------------------------------
#define PROJ_SMEM 98304

__global__ __launch_bounds__(256, 2) void proj_tc()
{
    extern __shared__ __align__(128) char smem[];
    const uint32_t sb = smem_u32(smem);

    const int tid  = threadIdx.x;
    const int warp = tid >> 5;
    const int lane = tid & 31;
    const int warp_m = warp >> 1;
    const int warp_n = warp & 1;
    const int p    = blockIdx.x;
    const int row0 = blockIdx.y * 128;

    const __half* wt = g_wt + (size_t)p * H_SZ * C_SZ;

    float D[2][8][4];
#pragma unroll
    for (int i = 0; i < 2; i++)
#pragma unroll
        for (int j = 0; j < 8; j++)
#pragma unroll
            for (int e = 0; e < 4; e++) D[i][j][e] = 0.0f;

    // One commit group per chunk: A-hi + A-lo + B.
    auto issueAB = [&](int c, int buf) {
        const int k0 = c * 64;
        const uint32_t aBase = sb + (uint32_t)buf * 32768;
        const uint32_t bBase = sb + 65536 + (uint32_t)buf * 16384;
#pragma unroll
        for (int it = 0; it < 4; it++) {
            int idx = it * 256 + tid;       // 0..1023
            int row = idx >> 3;
            int ch  = idx & 7;
            uint32_t soff = (uint32_t)(row * 128 + ((ch ^ (row & 7)) << 4));
            size_t ga = (size_t)(row0 + row) * C_SZ + k0 + ch * 8;
            cp16(aBase + soff,         &g_xh[ga]);
            cp16(aBase + 16384 + soff, &g_xl[ga]);
            cp16(bBase + soff, &wt[(size_t)row * C_SZ + k0 + ch * 8]);  // row==n
        }
        CP_COMMIT();
    };

    issueAB(0, 0);

    for (int c = 0; c < 16; c++) {
        if (c < 15) issueAB(c + 1, (c + 1) & 1);
        else        CP_COMMIT();            // keep group count uniform
        CP_WAIT1();                         // chunk c resident
        __syncthreads();

        const uint32_t aB = sb + (uint32_t)(c & 1) * 32768;
        const uint32_t bB = sb + 65536 + (uint32_t)(c & 1) * 16384;
#pragma unroll
        for (int ks = 0; ks < 4; ks++) {
            const int ch0 = ks * 2;
            uint32_t ah[2][4], al[2][4];
#pragma unroll
            for (int mf = 0; mf < 2; mf++) {
                int row = warp_m * 32 + mf * 16 + (lane & 15);
                int ch  = ch0 + (lane >> 4);
                uint32_t off = (uint32_t)(row * 128 + ((ch ^ (row & 7)) << 4));
                ldsm4(ah[mf], aB + off);
                ldsm4(al[mf], aB + 16384 + off);
            }
#pragma unroll
            for (int np = 0; np < 4; np++) {
                int nrow = warp_n * 64 + np * 16 + (lane & 7) + ((lane >> 4) << 3);
                int ch   = ch0 + ((lane >> 3) & 1);
                uint32_t off = (uint32_t)(nrow * 128 + ((ch ^ (nrow & 7)) << 4));
                uint32_t bw[4];
                ldsm4(bw, bB + off);
#pragma unroll
                for (int mf = 0; mf < 2; mf++) {
                    mma16816h(D[mf][2 * np],     ah[mf], bw[0], bw[1]);
                    mma16816h(D[mf][2 * np],     al[mf], bw[0], bw[1]);
                    mma16816h(D[mf][2 * np + 1], ah[mf], bw[2], bw[3]);
                    mma16816h(D[mf][2 * np + 1], al[mf], bw[2], bw[3]);
                }
            }
        }
        __syncthreads();   // compute done before buffer (c&1) is re-staged
    }
    CP_WAIT0();

    // Epilogue: q -> fp16 split (scaled by 1/32); k/v -> fp16 single
    const int gid = lane >> 2;
    const int cb  = 2 * (lane & 3);
    if (p == 0) {
#pragma unroll
        for (int mf = 0; mf < 2; mf++) {
            int r0 = row0 + warp_m * 32 + mf * 16 + gid;
            int r1 = r0 + 8;
#pragma unroll
            for (int nf = 0; nf < 8; nf++) {
                int col = warp_n * 64 + nf * 8 + cb;
                float v0 = D[mf][nf][0] * SCALE, v1 = D[mf][nf][1] * SCALE;
                float v2 = D[mf][nf][2] * SCALE, v3 = D[mf][nf][3] * SCALE;
                uint32_t h01, l01, h23, l23;
                split_h2(v0, v1, h01, l01);
                split_h2(v2, v3, h23, l23);
                *(uint32_t*)&g_qh[(size_t)r0 * H_SZ + col] = h01;
                *(uint32_t*)&g_ql[(size_t)r0 * H_SZ + col] = l01;
                *(uint32_t*)&g_qh[(size_t)r1 * H_SZ + col] = h23;
                *(uint32_t*)&g_ql[(size_t)r1 * H_SZ + col] = l23;
            }
        }
    } else {
        __half* dst = (p == 1) ? g_kx : g_vx;
#pragma unroll
        for (int mf = 0; mf < 2; mf++) {
            int r0 = row0 + warp_m * 32 + mf * 16 + gid;
            int r1 = r0 + 8;
#pragma unroll
            for (int nf = 0; nf < 8; nf++) {
                int col = warp_n * 64 + nf * 8 + cb;
                __half2 a = __floats2half2_rn(D[mf][nf][0], D[mf][nf][1]);
                __half2 b = __floats2half2_rn(D[mf][nf][2], D[mf][nf][3]);
                *(uint32_t*)&dst[(size_t)r0 * H_SZ + col] = *(uint32_t*)&a;
                *(uint32_t*)&dst[(size_t)r1 * H_SZ + col] = *(uint32_t*)&b;
            }
        }
    }
}

// ---------------------------------------------------------------------------
// attn_tc: flash attention, fp16 asymmetric split (unchanged from R13):
//   S = Qh·K + Ql·K ; O = Ph·V + Pl·V
// One 64-row q-tile per CTA, 4 warps, CK=64, grid 256 heavy-first pairing.
// K and V double-buffered via cp.async, full-chunk prefetch distance.
// ---------------------------------------------------------------------------
#define AT_SMEM 98304

__global__ __launch_bounds__(128, 2) void attn_tc(float* __restrict__ out)
{
    extern __shared__ __align__(128) char smem[];
    const uint32_t sb  = smem_u32(smem);
    const uint32_t sQh = sb;
    const uint32_t sQl = sb + 16384;
    const uint32_t sK  = sb + 32768;   // + 16384*buf
    const uint32_t sV  = sb + 65536;   // + 16384*buf

    const int tid  = threadIdx.x;
    const int warp = tid >> 5;
    const int lane = tid & 31;
    const int gid  = lane >> 2;
    const int cb   = 2 * (lane & 3);

    const int bid  = blockIdx.x;
    const int rank = (bid < 148) ? bid : 403 - bid;
    const int tile = 31 - (rank >> 3);
    const int b    = rank & 7;
    const int t0   = tile * 64;
    const int nchunks = tile + 1;

    const size_t bbase = (size_t)b * T_SZ * H_SZ;

    auto stage1 = [&](int r0, uint32_t dst, const __half* src) {
#pragma unroll
        for (int it = 0; it < 8; it++) {
            int idx = it * 128 + tid;
            int row = idx >> 4;
            int ch  = idx & 15;
            uint32_t soff = (uint32_t)(row * 256 + ((ch ^ (row & 7)) << 4));
            cp16(dst + soff, &src[bbase + (size_t)(r0 + row) * H_SZ + ch * 8]);
        }
    };

    // Preload Q + K(0) + V(0), one group
    stage1(t0, sQh, g_qh);
    stage1(t0, sQl, g_ql);
    stage1(0,  sK,  g_kx);
    stage1(0,  sV,  g_vx);
    CP_COMMIT();

    float O[16][4];
#pragma unroll
    for (int i = 0; i < 16; i++)
#pragma unroll
        for (int e = 0; e < 4; e++) O[i][e] = 0.0f;
    float mr0 = -1e30f, mr1 = -1e30f, lr0 = 0.0f, lr1 = 0.0f;

    for (int c = 0; c < nchunks; c++) {
        CP_WAIT0();          // chunk c data ready
        __syncthreads();     // + everyone done with buffer (c+1)&1 (chunk c-1)

        if (c + 1 < nchunks) {   // prefetch next chunk under full compute
            int nb = (c + 1) & 1;
            stage1((c + 1) * 64, sK + nb * 16384, g_kx);
            stage1((c + 1) * 64, sV + nb * 16384, g_vx);
        }
        CP_COMMIT();

        const uint32_t kB = sK + (uint32_t)(c & 1) * 16384;
        const uint32_t vB = sV + (uint32_t)(c & 1) * 16384;

        // ---- S = Qh·K + Ql·K ----
        float S[8][4];
#pragma unroll
        for (int i = 0; i < 8; i++)
#pragma unroll
            for (int e = 0; e < 4; e++) S[i][e] = 0.0f;

#pragma unroll
        for (int kf = 0; kf < 8; kf++) {
            const int ch0 = kf * 2;
            uint32_t ah[4], al[4];
            {
                int row = warp * 16 + (lane & 15);
                int ch  = ch0 + (lane >> 4);
                uint32_t off = (uint32_t)(row * 256 + ((ch ^ (row & 7)) << 4));
                ldsm4(ah, sQh + off);
                ldsm4(al, sQl + off);
            }
#pragma unroll
            for (int np = 0; np < 4; np++) {
                int nrow = np * 16 + (lane & 7) + ((lane >> 4) << 3);
                int ch   = ch0 + ((lane >> 3) & 1);
                uint32_t off = (uint32_t)(nrow * 256 + ((ch ^ (nrow & 7)) << 4));
                uint32_t bk[4];
                ldsm4(bk, kB + off);
                mma16816h(S[2 * np],     ah, bk[0], bk[1]);
                mma16816h(S[2 * np],     al, bk[0], bk[1]);
                mma16816h(S[2 * np + 1], ah, bk[2], bk[3]);
                mma16816h(S[2 * np + 1], al, bk[2], bk[3]);
            }
        }

        // ---- causal mask (only final chunk is diagonal) ----
        if (c == nchunks - 1) {
            int r0 = warp * 16 + gid;
#pragma unroll
            for (int nf = 0; nf < 8; nf++) {
                int j0 = nf * 8 + cb;
                if (j0     > r0)     S[nf][0] = -1e30f;
                if (j0 + 1 > r0)     S[nf][1] = -1e30f;
                if (j0     > r0 + 8) S[nf][2] = -1e30f;
                if (j0 + 1 > r0 + 8) S[nf][3] = -1e30f;
            }
        }

        // ---- online softmax ----
        float mx0 = mr0, mx1 = mr1;
#pragma unroll
        for (int nf = 0; nf < 8; nf++) {
            mx0 = fmaxf(mx0, fmaxf(S[nf][0], S[nf][1]));
            mx1 = fmaxf(mx1, fmaxf(S[nf][2], S[nf][3]));
        }
        mx0 = fmaxf(mx0, __shfl_xor_sync(0xffffffffu, mx0, 1));
        mx0 = fmaxf(mx0, __shfl_xor_sync(0xffffffffu, mx0, 2));
        mx1 = fmaxf(mx1, __shfl_xor_sync(0xffffffffu, mx1, 1));
        mx1 = fmaxf(mx1, __shfl_xor_sync(0xffffffffu, mx1, 2));
        float corr0 = __expf(mr0 - mx0);
        float corr1 = __expf(mr1 - mx1);
        float sum0 = 0.0f, sum1 = 0.0f;
#pragma unroll
        for (int nf = 0; nf < 8; nf++) {
            S[nf][0] = __expf(S[nf][0] - mx0); sum0 += S[nf][0];
            S[nf][1] = __expf(S[nf][1] - mx0); sum0 += S[nf][1];
            S[nf][2] = __expf(S[nf][2] - mx1); sum1 += S[nf][2];
            S[nf][3] = __expf(S[nf][3] - mx1); sum1 += S[nf][3];
        }
        sum0 += __shfl_xor_sync(0xffffffffu, sum0, 1);
        sum0 += __shfl_xor_sync(0xffffffffu, sum0, 2);
        sum1 += __shfl_xor_sync(0xffffffffu, sum1, 1);
        sum1 += __shfl_xor_sync(0xffffffffu, sum1, 2);
        lr0 = lr0 * corr0 + sum0;  mr0 = mx0;
        lr1 = lr1 * corr1 + sum1;  mr1 = mx1;
#pragma unroll
        for (int nf = 0; nf < 16; nf++) {
            O[nf][0] *= corr0; O[nf][1] *= corr0;
            O[nf][2] *= corr1; O[nf][3] *= corr1;
        }

        // ---- O += Ph·V + Pl·V ----
#pragma unroll
        for (int kf = 0; kf < 4; kf++) {
            uint32_t ph[4], pl[4];
            split_h2(S[2*kf][0],   S[2*kf][1],   ph[0], pl[0]);
            split_h2(S[2*kf][2],   S[2*kf][3],   ph[1], pl[1]);
            split_h2(S[2*kf+1][0], S[2*kf+1][1], ph[2], pl[2]);
            split_h2(S[2*kf+1][2], S[2*kf+1][3], ph[3], pl[3]);
#pragma unroll
            for (int np = 0; np < 8; np++) {
                int row = kf * 16 + (lane & 7) + (((lane >> 3) & 1) << 3);
                int ch  = np * 2 + (lane >> 4);
                uint32_t off = (uint32_t)(row * 256 + ((ch ^ (row & 7)) << 4));
                uint32_t vv[4];
                ldsm4t(vv, vB + off);
                mma16816h(O[2 * np],     ph, vv[0], vv[1]);
                mma16816h(O[2 * np],     pl, vv[0], vv[1]);
                mma16816h(O[2 * np + 1], ph, vv[2], vv[3]);
                mma16816h(O[2 * np + 1], pl, vv[2], vv[3]);
            }
        }
    }
    CP_WAIT0();

    // ---- finalize + store ----
    float inv0 = 1.0f / lr0;
    float inv1 = 1.0f / lr1;
    size_t rg0 = (size_t)b * T_SZ + t0 + warp * 16 + gid;
    size_t rg1 = rg0 + 8;
#pragma unroll
    for (int nf = 0; nf < 16; nf++) {
        int col = nf * 8 + cb;
        float2 v0 = make_float2(O[nf][0] * inv0, O[nf][1] * inv0);
        float2 v1 = make_float2(O[nf][2] * inv1, O[nf][3] * inv1);
        *(float2*)&out[rg0 * H_SZ + col] = v0;
        *(float2*)&out[rg1 * H_SZ + col] = v1;
    }
}

// ---------------------------------------------------------------------------
extern "C" void kernel_launch(void* const* d_in, const int* in_sizes, int n_in,
                              void* d_out, int out_size)
{
    const float* x  = (const float*)d_in[0];   // [8,2048,1024]
    const float* Wq = (const float*)d_in[1];   // [1024,128]
    const float* Wk = (const float*)d_in[2];
    const float* Wv = (const float*)d_in[3];
    float* out = (float*)d_out;                // [8,2048,128]

    cudaFuncSetAttribute(proj_tc, cudaFuncAttributeMaxDynamicSharedMemorySize,
                         PROJ_SMEM);
    cudaFuncSetAttribute(attn_tc, cudaFuncAttributeMaxDynamicSharedMemorySize,
                         AT_SMEM);

    prep_x<<<(ROWS * C_SZ / 4) / 256, 256>>>(x);
    prep_w<<<(3 * H_SZ * C_SZ) / 256, 256>>>(Wq, Wk, Wv);
    proj_tc<<<dim3(3, ROWS / 128), 256, PROJ_SMEM>>>();
    attn_tc<<<256, 128, AT_SMEM>>>(out);
}

// round 17
// speedup vs baseline: 9.0164x; 1.3903x over previous
#include <cuda_runtime.h>
#include <cuda_fp16.h>
#include <cstdint>

// Problem constants
#define B_SZ   8
#define T_SZ   2048
#define C_SZ   1024
#define H_SZ   128
#define ROWS   (B_SZ * T_SZ)       // 16384
#define SCALE  (0.03125f)          // C^-0.5 = 1/32

// Scratch (device statics: allocation-free rule)
__device__ __half g_x16[ROWS * C_SZ];    // x single fp16
__device__ __half g_wt[3 * H_SZ * C_SZ]; // W^T single fp16: [proj][n][k]
__device__ __half g_qx[ROWS * H_SZ];     // q/32, fp16 single
__device__ __half g_kx[ROWS * H_SZ];     // k, fp16 single
__device__ __half g_vx[ROWS * H_SZ];     // v, fp16 single

// ---------------------------------------------------------------------------
// Helpers
// ---------------------------------------------------------------------------
__device__ __forceinline__ uint32_t smem_u32(const void* p) {
    uint32_t a;
    asm("{ .reg .u64 t; cvta.to.shared.u64 t, %1; cvt.u32.u64 %0, t; }"
        : "=r"(a) : "l"(p));
    return a;
}
__device__ __forceinline__ void ldsm4(uint32_t* r, uint32_t addr) {
    asm volatile("ldmatrix.sync.aligned.m8n8.x4.shared.b16 {%0,%1,%2,%3}, [%4];"
                 : "=r"(r[0]), "=r"(r[1]), "=r"(r[2]), "=r"(r[3]) : "r"(addr));
}
__device__ __forceinline__ void ldsm4t(uint32_t* r, uint32_t addr) {
    asm volatile("ldmatrix.sync.aligned.m8n8.x4.trans.shared.b16 {%0,%1,%2,%3}, [%4];"
                 : "=r"(r[0]), "=r"(r[1]), "=r"(r[2]), "=r"(r[3]) : "r"(addr));
}
__device__ __forceinline__ void mma16816h(float* d, const uint32_t* a,
                                          uint32_t b0, uint32_t b1) {
    asm volatile(
        "mma.sync.aligned.m16n8k16.row.col.f32.f16.f16.f32 "
        "{%0,%1,%2,%3}, {%4,%5,%6,%7}, {%8,%9}, {%0,%1,%2,%3};"
        : "+f"(d[0]), "+f"(d[1]), "+f"(d[2]), "+f"(d[3])
        : "r"(a[0]), "r"(a[1]), "r"(a[2]), "r"(a[3]), "r"(b0), "r"(b1));
}
// split (a,b) fp32 -> fp16 hi pair + fp16 residual pair
__device__ __forceinline__ void split_h2(float a, float b,
                                         uint32_t& h, uint32_t& l) {
    __half2 hh = __floats2half2_rn(a, b);
    float2 hf = __half22float2(hh);
    __half2 ll = __floats2half2_rn(a - hf.x, b - hf.y);
    h = *reinterpret_cast<uint32_t*>(&hh);
    l = *reinterpret_cast<uint32_t*>(&ll);
}
__device__ __forceinline__ uint32_t pack_h2(float a, float b) {
    __half2 hh = __floats2half2_rn(a, b);
    return *reinterpret_cast<uint32_t*>(&hh);
}
__device__ __forceinline__ void cp16(uint32_t dst, const void* src) {
    asm volatile("cp.async.cg.shared.global [%0], [%1], 16;"
                 :: "r"(dst), "l"(src));
}
#define CP_COMMIT() asm volatile("cp.async.commit_group;" ::: "memory")
#define CP_WAIT0()  asm volatile("cp.async.wait_group 0;" ::: "memory")
#define CP_WAIT1()  asm volatile("cp.async.wait_group 1;" ::: "memory")

// ---------------------------------------------------------------------------
// prep_x: convert x (fp32) to single fp16 (memory-bound, once)
// ---------------------------------------------------------------------------
__global__ __launch_bounds__(256) void prep_x(const float* __restrict__ x)
{
    size_t i = (size_t)blockIdx.x * 256 + threadIdx.x;   // float4 index
    float4 v = ((const float4*)x)[i];
    *(uint2*)&g_x16[4 * i] = make_uint2(pack_h2(v.x, v.y), pack_h2(v.z, v.w));
}

// ---------------------------------------------------------------------------
// prep_w: transpose W to fp16 single: g_wt[p][n][k] = fp16(W_p[k][n])
// ---------------------------------------------------------------------------
__global__ __launch_bounds__(256) void prep_w(const float* __restrict__ Wq,
                                              const float* __restrict__ Wk,
                                              const float* __restrict__ Wv)
{
    int i = blockIdx.x * 256 + threadIdx.x;   // 0 .. 3*131072-1
    int p   = i >> 17;
    int rem = i & 131071;
    int n = rem >> 10;
    int k = rem & 1023;
    const float* W = (p == 0) ? Wq : (p == 1) ? Wk : Wv;
    g_wt[i] = __float2half(W[k * H_SZ + n]);
}

// ---------------------------------------------------------------------------
// proj_tc: q/k/v = x @ W, plain fp16 mma.sync (1 MMA/frag, fp32 accum).
// BM=128, BN=128, BK=64. Grid (3, 128), 256 threads. A and B double-buffered
// via cp.async, one commit group per chunk, wait_group 1.
// Smem: A0@0 A1@16K B0@32K B1@48K = 64KB.
// Rows: 64 fp16 = 128B = 8 chunks of 16B, XOR-swizzled: chunk ^= row&7.
// Epilogue: q scaled by 1/32; all outputs single fp16.
// ---------------------------------------------------------------------------
#define PROJ_SMEM 65536

__global__ __launch_bounds__(256, 2) void proj_tc()
{
    extern __shared__ __align__(128) char smem[];
    const uint32_t sb = smem_u32(smem);

    const int tid  = threadIdx.x;
    const int warp = tid >> 5;
    const int lane = tid & 31;
    const int warp_m = warp >> 1;
    const int warp_n = warp & 1;
    const int p    = blockIdx.x;
    const int row0 = blockIdx.y * 128;

    const __half* wt = g_wt + (size_t)p * H_SZ * C_SZ;

    float D[2][8][4];
#pragma unroll
    for (int i = 0; i < 2; i++)
#pragma unroll
        for (int j = 0; j < 8; j++)
#pragma unroll
            for (int e = 0; e < 4; e++) D[i][j][e] = 0.0f;

    // One commit group per chunk: A + B.
    auto issueAB = [&](int c, int buf) {
        const int k0 = c * 64;
        const uint32_t aBase = sb + (uint32_t)buf * 16384;
        const uint32_t bBase = sb + 32768 + (uint32_t)buf * 16384;
#pragma unroll
        for (int it = 0; it < 4; it++) {
            int idx = it * 256 + tid;       // 0..1023
            int row = idx >> 3;
            int ch  = idx & 7;
            uint32_t soff = (uint32_t)(row * 128 + ((ch ^ (row & 7)) << 4));
            cp16(aBase + soff, &g_x16[(size_t)(row0 + row) * C_SZ + k0 + ch * 8]);
            cp16(bBase + soff, &wt[(size_t)row * C_SZ + k0 + ch * 8]);  // row==n
        }
        CP_COMMIT();
    };

    issueAB(0, 0);

    for (int c = 0; c < 16; c++) {
        if (c < 15) issueAB(c + 1, (c + 1) & 1);
        else        CP_COMMIT();            // keep group count uniform
        CP_WAIT1();                         // chunk c resident
        __syncthreads();

        const uint32_t aB = sb + (uint32_t)(c & 1) * 16384;
        const uint32_t bB = sb + 32768 + (uint32_t)(c & 1) * 16384;
#pragma unroll
        for (int ks = 0; ks < 4; ks++) {
            const int ch0 = ks * 2;
            uint32_t ah[2][4];
#pragma unroll
            for (int mf = 0; mf < 2; mf++) {
                int row = warp_m * 32 + mf * 16 + (lane & 15);
                int ch  = ch0 + (lane >> 4);
                uint32_t off = (uint32_t)(row * 128 + ((ch ^ (row & 7)) << 4));
                ldsm4(ah[mf], aB + off);
            }
#pragma unroll
            for (int np = 0; np < 4; np++) {
                int nrow = warp_n * 64 + np * 16 + (lane & 7) + ((lane >> 4) << 3);
                int ch   = ch0 + ((lane >> 3) & 1);
                uint32_t off = (uint32_t)(nrow * 128 + ((ch ^ (nrow & 7)) << 4));
                uint32_t bw[4];
                ldsm4(bw, bB + off);
#pragma unroll
                for (int mf = 0; mf < 2; mf++) {
                    mma16816h(D[mf][2 * np],     ah[mf], bw[0], bw[1]);
                    mma16816h(D[mf][2 * np + 1], ah[mf], bw[2], bw[3]);
                }
            }
        }
        __syncthreads();   // compute done before buffer (c&1) is re-staged
    }
    CP_WAIT0();

    // Epilogue: single fp16 (q scaled by 1/32)
    __half* dst = (p == 0) ? g_qx : (p == 1) ? g_kx : g_vx;
    const float sc = (p == 0) ? SCALE : 1.0f;
    const int gid = lane >> 2;
    const int cb  = 2 * (lane & 3);
#pragma unroll
    for (int mf = 0; mf < 2; mf++) {
        int r0 = row0 + warp_m * 32 + mf * 16 + gid;
        int r1 = r0 + 8;
#pragma unroll
        for (int nf = 0; nf < 8; nf++) {
            int col = warp_n * 64 + nf * 8 + cb;
            *(uint32_t*)&dst[(size_t)r0 * H_SZ + col] =
                pack_h2(D[mf][nf][0] * sc, D[mf][nf][1] * sc);
            *(uint32_t*)&dst[(size_t)r1 * H_SZ + col] =
                pack_h2(D[mf][nf][2] * sc, D[mf][nf][3] * sc);
        }
    }
}

// ---------------------------------------------------------------------------
// attn_tc: flash attention:
//   S = Q·K       (both single fp16)        -> 1 MMA/frag
//   O = Ph·V+Pl·V (P split fp16, V single)  -> 2 MMAs/frag
// One 64-row q-tile per CTA, 4 warps, CK=64, grid 256 heavy-first pairing.
// K and V double-buffered via cp.async, full-chunk prefetch distance.
// Smem: Q 16K | K x2 16K | V x2 16K = 80KB. Rows 256B = 16 chunks of 16B,
// XOR swizzle chunk ^= row&7.
// ---------------------------------------------------------------------------
#define AT_SMEM 81920

__global__ __launch_bounds__(128, 2) void attn_tc(float* __restrict__ out)
{
    extern __shared__ __align__(128) char smem[];
    const uint32_t sb = smem_u32(smem);
    const uint32_t sQ = sb;
    const uint32_t sK = sb + 16384;   // + 16384*buf
    const uint32_t sV = sb + 49152;   // + 16384*buf

    const int tid  = threadIdx.x;
    const int warp = tid >> 5;
    const int lane = tid & 31;
    const int gid  = lane >> 2;
    const int cb   = 2 * (lane & 3);

    const int bid  = blockIdx.x;
    const int rank = (bid < 148) ? bid : 403 - bid;
    const int tile = 31 - (rank >> 3);
    const int b    = rank & 7;
    const int t0   = tile * 64;
    const int nchunks = tile + 1;

    const size_t bbase = (size_t)b * T_SZ * H_SZ;

    auto stage1 = [&](int r0, uint32_t dst, const __half* src) {
#pragma unroll
        for (int it = 0; it < 8; it++) {
            int idx = it * 128 + tid;
            int row = idx >> 4;
            int ch  = idx & 15;
            uint32_t soff = (uint32_t)(row * 256 + ((ch ^ (row & 7)) << 4));
            cp16(dst + soff, &src[bbase + (size_t)(r0 + row) * H_SZ + ch * 8]);
        }
    };

    // Preload Q + K(0) + V(0), one group
    stage1(t0, sQ, g_qx);
    stage1(0,  sK, g_kx);
    stage1(0,  sV, g_vx);
    CP_COMMIT();

    float O[16][4];
#pragma unroll
    for (int i = 0; i < 16; i++)
#pragma unroll
        for (int e = 0; e < 4; e++) O[i][e] = 0.0f;
    float mr0 = -1e30f, mr1 = -1e30f, lr0 = 0.0f, lr1 = 0.0f;

    for (int c = 0; c < nchunks; c++) {
        CP_WAIT0();          // chunk c data ready
        __syncthreads();     // + everyone done with buffer (c+1)&1 (chunk c-1)

        if (c + 1 < nchunks) {   // prefetch next chunk under full compute
            int nb = (c + 1) & 1;
            stage1((c + 1) * 64, sK + nb * 16384, g_kx);
            stage1((c + 1) * 64, sV + nb * 16384, g_vx);
        }
        CP_COMMIT();

        const uint32_t kB = sK + (uint32_t)(c & 1) * 16384;
        const uint32_t vB = sV + (uint32_t)(c & 1) * 16384;

        // ---- S = Q·K ----
        float S[8][4];
#pragma unroll
        for (int i = 0; i < 8; i++)
#pragma unroll
            for (int e = 0; e < 4; e++) S[i][e] = 0.0f;

#pragma unroll
        for (int kf = 0; kf < 8; kf++) {
            const int ch0 = kf * 2;
            uint32_t ah[4];
            {
                int row = warp * 16 + (lane & 15);
                int ch  = ch0 + (lane >> 4);
                uint32_t off = (uint32_t)(row * 256 + ((ch ^ (row & 7)) << 4));
                ldsm4(ah, sQ + off);
            }
#pragma unroll
            for (int np = 0; np < 4; np++) {
                int nrow = np * 16 + (lane & 7) + ((lane >> 4) << 3);
                int ch   = ch0 + ((lane >> 3) & 1);
                uint32_t off = (uint32_t)(nrow * 256 + ((ch ^ (nrow & 7)) << 4));
                uint32_t bk[4];
                ldsm4(bk, kB + off);
                mma16816h(S[2 * np],     ah, bk[0], bk[1]);
                mma16816h(S[2 * np + 1], ah, bk[2], bk[3]);
            }
        }

        // ---- causal mask (only final chunk is diagonal) ----
        if (c == nchunks - 1) {
            int r0 = warp * 16 + gid;
#pragma unroll
            for (int nf = 0; nf < 8; nf++) {
                int j0 = nf * 8 + cb;
                if (j0     > r0)     S[nf][0] = -1e30f;
                if (j0 + 1 > r0)     S[nf][1] = -1e30f;
                if (j0     > r0 + 8) S[nf][2] = -1e30f;
                if (j0 + 1 > r0 + 8) S[nf][3] = -1e30f;
            }
        }

        // ---- online softmax ----
        float mx0 = mr0, mx1 = mr1;
#pragma unroll
        for (int nf = 0; nf < 8; nf++) {
            mx0 = fmaxf(mx0, fmaxf(S[nf][0], S[nf][1]));
            mx1 = fmaxf(mx1, fmaxf(S[nf][2], S[nf][3]));
        }
        mx0 = fmaxf(mx0, __shfl_xor_sync(0xffffffffu, mx0, 1));
        mx0 = fmaxf(mx0, __shfl_xor_sync(0xffffffffu, mx0, 2));
        mx1 = fmaxf(mx1, __shfl_xor_sync(0xffffffffu, mx1, 1));
        mx1 = fmaxf(mx1, __shfl_xor_sync(0xffffffffu, mx1, 2));
        float corr0 = __expf(mr0 - mx0);
        float corr1 = __expf(mr1 - mx1);
        float sum0 = 0.0f, sum1 = 0.0f;
#pragma unroll
        for (int nf = 0; nf < 8; nf++) {
            S[nf][0] = __expf(S[nf][0] - mx0); sum0 += S[nf][0];
            S[nf][1] = __expf(S[nf][1] - mx0); sum0 += S[nf][1];
            S[nf][2] = __expf(S[nf][2] - mx1); sum1 += S[nf][2];
            S[nf][3] = __expf(S[nf][3] - mx1); sum1 += S[nf][3];
        }
        sum0 += __shfl_xor_sync(0xffffffffu, sum0, 1);
        sum0 += __shfl_xor_sync(0xffffffffu, sum0, 2);
        sum1 += __shfl_xor_sync(0xffffffffu, sum1, 1);
        sum1 += __shfl_xor_sync(0xffffffffu, sum1, 2);
        lr0 = lr0 * corr0 + sum0;  mr0 = mx0;
        lr1 = lr1 * corr1 + sum1;  mr1 = mx1;
#pragma unroll
        for (int nf = 0; nf < 16; nf++) {
            O[nf][0] *= corr0; O[nf][1] *= corr0;
            O[nf][2] *= corr1; O[nf][3] *= corr1;
        }

        // ---- O += Ph·V + Pl·V ----
#pragma unroll
        for (int kf = 0; kf < 4; kf++) {
            uint32_t ph[4], pl[4];
            split_h2(S[2*kf][0],   S[2*kf][1],   ph[0], pl[0]);
            split_h2(S[2*kf][2],   S[2*kf][3],   ph[1], pl[1]);
            split_h2(S[2*kf+1][0], S[2*kf+1][1], ph[2], pl[2]);
            split_h2(S[2*kf+1][2], S[2*kf+1][3], ph[3], pl[3]);
#pragma unroll
            for (int np = 0; np < 8; np++) {
                int row = kf * 16 + (lane & 7) + (((lane >> 3) & 1) << 3);
                int ch  = np * 2 + (lane >> 4);
                uint32_t off = (uint32_t)(row * 256 + ((ch ^ (row & 7)) << 4));
                uint32_t vv[4];
                ldsm4t(vv, vB + off);
                mma16816h(O[2 * np],     ph, vv[0], vv[1]);
                mma16816h(O[2 * np],     pl, vv[0], vv[1]);
                mma16816h(O[2 * np + 1], ph, vv[2], vv[3]);
                mma16816h(O[2 * np + 1], pl, vv[2], vv[3]);
            }
        }
    }
    CP_WAIT0();

    // ---- finalize + store ----
    float inv0 = 1.0f / lr0;
    float inv1 = 1.0f / lr1;
    size_t rg0 = (size_t)b * T_SZ + t0 + warp * 16 + gid;
    size_t rg1 = rg0 + 8;
#pragma unroll
    for (int nf = 0; nf < 16; nf++) {
        int col = nf * 8 + cb;
        float2 v0 = make_float2(O[nf][0] * inv0, O[nf][1] * inv0);
        float2 v1 = make_float2(O[nf][2] * inv1, O[nf][3] * inv1);
        *(float2*)&out[rg0 * H_SZ + col] = v0;
        *(float2*)&out[rg1 * H_SZ + col] = v1;
    }
}

// ---------------------------------------------------------------------------
extern "C" void kernel_launch(void* const* d_in, const int* in_sizes, int n_in,
                              void* d_out, int out_size)
{
    const float* x  = (const float*)d_in[0];   // [8,2048,1024]
    const float* Wq = (const float*)d_in[1];   // [1024,128]
    const float* Wk = (const float*)d_in[2];
    const float* Wv = (const float*)d_in[3];
    float* out = (float*)d_out;                // [8,2048,128]

    cudaFuncSetAttribute(proj_tc, cudaFuncAttributeMaxDynamicSharedMemorySize,
                         PROJ_SMEM);
    cudaFuncSetAttribute(attn_tc, cudaFuncAttributeMaxDynamicSharedMemorySize,
                         AT_SMEM);

    prep_x<<<(ROWS * C_SZ / 4) / 256, 256>>>(x);
    prep_w<<<(3 * H_SZ * C_SZ) / 256, 256>>>(Wq, Wk, Wv);
    proj_tc<<<dim3(3, ROWS / 128), 256, PROJ_SMEM>>>();
    attn_tc<<<256, 128, AT_SMEM>>>(out);
}